// round 13
// baseline (speedup 1.0000x reference)
#include <cuda_runtime.h>
#include <cuda_bf16.h>
#include <cuda_fp16.h>
#include <math.h>
#include <cstdint>

// ---------------- problem constants ----------------
#define T_DIM 4096
#define S_DIM 4096
#define B_DIM 8
#define E_DIM 1024
#define BUCKET 16
#define NB 256            // T/BUCKET
#define TAU 0.75f
#define ATTN_ALPHA (1.0f/(32.0f*0.75f))
#define QK_STRIDE (B_DIM*NB*E_DIM)   // 2097152

// ---------------- scratch (device globals; no allocation allowed) ----------------
__device__ __half g_qkmh[2*QK_STRIDE];      // bucket means q|k, fp16
__device__ __half g_qkbh[2*QK_STRIDE];      // projected bucket q|k, fp16
__device__ __half g_Wqkh[2*E_DIM*E_DIM];    // Wq|Wk fp16
__device__ __half g_Wvh[E_DIM*E_DIM];
__device__ __half g_Woh[E_DIM*E_DIM];
__device__ float g_bqk[2*E_DIM];            // bq|bk fp32
__device__ float g_la[B_DIM*NB*NB];
__device__ __half g_ph[B_DIM*NB*NB];        // sinkhorn result, fp16
__device__ float g_rowsum[B_DIM*NB];
__device__ int   g_kpmb[B_DIM*NB];
__device__ float g_bvo[E_DIM];              // Wo @ bv
__device__ __half g_vh[S_DIM*B_DIM*E_DIM];  // value in fp16
__device__ __half g_zh[T_DIM*B_DIM*E_DIM];  // mixed value, fp16 (rows m=t*8+b)
__device__ __half g_wvoh[E_DIM*E_DIM];      // Wo @ Wv in fp16

// =================== warp-MMA helpers (compute_80-compatible PTX) ===================
__device__ __forceinline__ uint32_t smem_u32(const void* p) {
    uint32_t a;
    asm("{ .reg .u64 t; cvta.to.shared.u64 t, %1; cvt.u32.u64 %0, t; }" : "=r"(a) : "l"(p));
    return a;
}

#define CP_ASYNC16(dst, src) \
    asm volatile("cp.async.cg.shared.global [%0], [%1], 16;" :: "r"(dst), "l"(src))
#define CP_COMMIT() asm volatile("cp.async.commit_group;")
#define CP_WAIT3()  asm volatile("cp.async.wait_group 3;")
#define CP_WAIT1()  asm volatile("cp.async.wait_group 1;")
#define CP_WAIT0()  asm volatile("cp.async.wait_group 0;")

#define LDSM_X4(r0, r1, r2, r3, addr) \
    asm volatile("ldmatrix.sync.aligned.m8n8.x4.shared.b16 {%0,%1,%2,%3}, [%4];" \
        : "=r"(r0), "=r"(r1), "=r"(r2), "=r"(r3) : "r"(addr))

#define LDSM_X4_T(r0, r1, r2, r3, addr) \
    asm volatile("ldmatrix.sync.aligned.m8n8.x4.trans.shared.b16 {%0,%1,%2,%3}, [%4];" \
        : "=r"(r0), "=r"(r1), "=r"(r2), "=r"(r3) : "r"(addr))

#define MMA16816F16(d, a0, a1, a2, a3, b0, b1) \
    asm volatile("mma.sync.aligned.m16n8k16.row.col.f32.f16.f16.f32 " \
        "{%0,%1,%2,%3}, {%4,%5,%6,%7}, {%8,%9}, {%0,%1,%2,%3};" \
        : "+f"((d)[0]), "+f"((d)[1]), "+f"((d)[2]), "+f"((d)[3]) \
        : "r"(a0), "r"(a1), "r"(a2), "r"(a3), "r"(b0), "r"(b1))

// =================== generic fp16 HMMA GEMM (frozen R7 core; lda + splitK added) ===================
// C[m,n] = alpha * sum_k A[m,k]*B'[n,k]  (+bias[n])   rows stride lda
// SPLITK: grid z = b*2+s; split s covers K columns [s*K, s*K+K); epilogue fp32 atomicAdd.
#define HG_A_ROW 80
#define HG_A_TILE (128*HG_A_ROW)   // 10240
#define HG_BT_ROW 272
#define HG_BT_TILE (32*HG_BT_ROW)  // 8704

template <bool BTRANS, bool BIAS, bool OUT_HALF, bool SPLITK>
__global__ __launch_bounds__(256)
void hgemm_kernel(void* __restrict__ Cv, const __half* __restrict__ A,
                  const __half* __restrict__ B, const float* __restrict__ bias,
                  int M, int N, int K, int lda, float alpha, long sA, long sB, long sC) {
    constexpr int B_TILE = BTRANS ? HG_BT_TILE : HG_A_TILE;
    constexpr int STAGE = HG_A_TILE + B_TILE;
    extern __shared__ char smem[];
    uint32_t sbase = smem_u32(smem);

    int z = blockIdx.z;
    long cofs;
    if (SPLITK) {
        int zb = z >> 1, zs = z & 1;
        A += (long)zb * sA + zs * K;
        B += (long)zb * sB + zs * K;
        cofs = (long)zb * sC;
    } else {
        A += (long)z * sA; B += (long)z * sB;
        cofs = (long)z * sC;
    }

    int tid = threadIdx.x, wid = tid >> 5, lane = tid & 31;
    int bm = blockIdx.y * 128, bn = blockIdx.x * 128;
    int wm = (wid & 1) * 64, wn = (wid >> 1) * 32;

    float acc[4][4][4];
#pragma unroll
    for (int i = 0; i < 4; i++)
#pragma unroll
        for (int j = 0; j < 4; j++)
#pragma unroll
            for (int r = 0; r < 4; r++) acc[i][j][r] = 0.f;

    auto stage_load = [&](int kt, int buf) {
        int k0 = kt * 32;
        uint32_t base = sbase + buf * STAGE;
#pragma unroll
        for (int q = 0; q < 2; q++) {
            int c = tid + q * 256;
            int row = c >> 2, seg = c & 3;
            CP_ASYNC16(base + row * HG_A_ROW + seg * 16,
                       A + (size_t)(bm + row) * lda + k0 + seg * 8);
        }
        if (!BTRANS) {
#pragma unroll
            for (int q = 0; q < 2; q++) {
                int c = tid + q * 256;
                int row = c >> 2, seg = c & 3;
                CP_ASYNC16(base + HG_A_TILE + row * HG_A_ROW + seg * 16,
                           B + (size_t)(bn + row) * lda + k0 + seg * 8);
            }
        } else {
#pragma unroll
            for (int q = 0; q < 2; q++) {
                int c = tid + q * 256;
                int kk = c >> 4, seg = c & 15;
                CP_ASYNC16(base + HG_A_TILE + kk * HG_BT_ROW + seg * 16,
                           B + (size_t)(k0 + kk) * N + bn + seg * 8);
            }
        }
        CP_COMMIT();
    };

    int lrow = lane & 15, lhi = lane >> 4;

    stage_load(0, 0);
    int NKT = K / 32;
    for (int kt = 0; kt < NKT; kt++) {
        if (kt + 1 < NKT) { stage_load(kt + 1, (kt + 1) & 1); CP_WAIT1(); }
        else CP_WAIT0();
        __syncthreads();

        uint32_t base = sbase + (kt & 1) * STAGE;
        uint32_t aS = base, bS = base + HG_A_TILE;

#pragma unroll
        for (int ks = 0; ks < 2; ks++) {
            uint32_t a[4][4], bt[2][4];
#pragma unroll
            for (int mt = 0; mt < 4; mt++) {
                uint32_t off = (wm + mt * 16 + lrow) * HG_A_ROW + (ks * 16 + lhi * 8) * 2;
                LDSM_X4(a[mt][0], a[mt][1], a[mt][2], a[mt][3], aS + off);
            }
            if (!BTRANS) {
#pragma unroll
                for (int nt = 0; nt < 2; nt++) {
                    uint32_t off = (wn + nt * 16 + lrow) * HG_A_ROW + (ks * 16 + lhi * 8) * 2;
                    LDSM_X4(bt[nt][0], bt[nt][1], bt[nt][2], bt[nt][3], bS + off);
                }
#pragma unroll
                for (int mt = 0; mt < 4; mt++)
#pragma unroll
                    for (int j = 0; j < 4; j++) {
                        int nt = j >> 1, hi = j & 1;
                        MMA16816F16(acc[mt][j], a[mt][0], a[mt][1], a[mt][2], a[mt][3],
                                    bt[nt][hi], bt[nt][hi + 2]);
                    }
            } else {
#pragma unroll
                for (int ng = 0; ng < 2; ng++) {
                    uint32_t off = (ks * 16 + lrow) * HG_BT_ROW + (wn + ng * 16 + lhi * 8) * 2;
                    LDSM_X4_T(bt[ng][0], bt[ng][1], bt[ng][2], bt[ng][3], bS + off);
                }
#pragma unroll
                for (int mt = 0; mt < 4; mt++)
#pragma unroll
                    for (int j = 0; j < 4; j++) {
                        int ng = j >> 1, hi = j & 1;
                        MMA16816F16(acc[mt][j], a[mt][0], a[mt][1], a[mt][2], a[mt][3],
                                    bt[ng][hi * 2], bt[ng][hi * 2 + 1]);
                    }
            }
        }
        __syncthreads();
    }

    // ---- epilogue ----
#pragma unroll
    for (int mt = 0; mt < 4; mt++) {
        int m0 = bm + wm + mt * 16 + (lane >> 2);
        int m1 = m0 + 8;
#pragma unroll
        for (int j = 0; j < 4; j++) {
            int n = bn + wn + j * 8 + (lane & 3) * 2;
            float v00 = acc[mt][j][0] * alpha, v01 = acc[mt][j][1] * alpha;
            float v10 = acc[mt][j][2] * alpha, v11 = acc[mt][j][3] * alpha;
            if (BIAS) {
                float b0 = bias[(long)blockIdx.z * N + n], b1 = bias[(long)blockIdx.z * N + n + 1];
                v00 += b0; v01 += b1; v10 += b0; v11 += b1;
            }
            if (SPLITK) {
                float* C = (float*)Cv + cofs;
                atomicAdd(C + (size_t)m0 * N + n, v00);
                atomicAdd(C + (size_t)m0 * N + n + 1, v01);
                atomicAdd(C + (size_t)m1 * N + n, v10);
                atomicAdd(C + (size_t)m1 * N + n + 1, v11);
            } else if (OUT_HALF) {
                __half* C = (__half*)Cv + cofs;
                *(__half2*)(C + (size_t)m0 * N + n) = __floats2half2_rn(v00, v01);
                *(__half2*)(C + (size_t)m1 * N + n) = __floats2half2_rn(v10, v11);
            } else {
                float* C = (float*)Cv + cofs;
                *(float2*)(C + (size_t)m0 * N + n) = make_float2(v00, v01);
                *(float2*)(C + (size_t)m1 * N + n) = make_float2(v10, v11);
            }
        }
    }
}

// =================== final GEMM (frozen champion config) ===================
#define KC 32
#define ROW_B 80
#define A_TILE_B (128*ROW_B)
#define B_TILE_B (256*ROW_B)
#define STAGE_B (A_TILE_B + B_TILE_B)
#define HMMA_SMEM (4*STAGE_B)

__global__ __launch_bounds__(256, 1)
void hmma_out_kernel(float* __restrict__ out,
                     const __half* __restrict__ Ah, const __half* __restrict__ Bh,
                     const float* __restrict__ bo, const float* __restrict__ bvo,
                     const float* __restrict__ rowsum) {
    extern __shared__ char smem[];
    uint32_t sbase = smem_u32(smem);

    int tid = threadIdx.x, wid = tid >> 5, lane = tid & 31;
    int bm = blockIdx.y * 128, bn = blockIdx.x * 256;
    int wm = (wid & 1) * 64, wn = (wid >> 1) * 64;

    const __half* Ag = Ah + (size_t)bm * 1024;
    const __half* Bg = Bh + (size_t)bn * 1024;

    float acc[4][8][4];
#pragma unroll
    for (int i = 0; i < 4; i++)
#pragma unroll
        for (int j = 0; j < 8; j++)
#pragma unroll
            for (int r = 0; r < 4; r++) acc[i][j][r] = 0.f;

    auto stage_load = [&](int kt, int buf) {
        int k0 = kt * KC;
        uint32_t base = sbase + buf * STAGE_B;
#pragma unroll
        for (int q = 0; q < 2; q++) {
            int c = tid + q * 256;
            int row = c >> 2, seg = c & 3;
            CP_ASYNC16(base + row * ROW_B + seg * 16,
                       Ag + (size_t)row * 1024 + k0 + seg * 8);
        }
#pragma unroll
        for (int q = 0; q < 4; q++) {
            int c = tid + q * 256;
            int row = c >> 2, seg = c & 3;
            CP_ASYNC16(base + A_TILE_B + row * ROW_B + seg * 16,
                       Bg + (size_t)row * 1024 + k0 + seg * 8);
        }
    };

    int lrow = lane & 15, lkseg = (lane >> 4) * 8;

    stage_load(0, 0); CP_COMMIT();
    stage_load(1, 1); CP_COMMIT();
    stage_load(2, 2); CP_COMMIT();

    const int NKT = 1024 / KC;
    for (int kt = 0; kt < NKT; kt++) {
        if (kt + 3 < NKT) stage_load(kt + 3, (kt + 3) & 3);
        CP_COMMIT();
        CP_WAIT3();
        __syncthreads();

        uint32_t base = sbase + (kt & 3) * STAGE_B;
        uint32_t aS = base, bS = base + A_TILE_B;

#pragma unroll
        for (int ks = 0; ks < KC / 16; ks++) {
            int kb = (ks * 16 + lkseg) * 2;
            uint32_t a[4][4], b[4][4];
#pragma unroll
            for (int mt = 0; mt < 4; mt++) {
                uint32_t off = (wm + mt * 16 + lrow) * ROW_B + kb;
                LDSM_X4(a[mt][0], a[mt][1], a[mt][2], a[mt][3], aS + off);
            }
#pragma unroll
            for (int nt = 0; nt < 4; nt++) {
                uint32_t off = (wn + nt * 16 + lrow) * ROW_B + kb;
                LDSM_X4(b[nt][0], b[nt][1], b[nt][2], b[nt][3], bS + off);
            }
#pragma unroll
            for (int mt = 0; mt < 4; mt++) {
#pragma unroll
                for (int j = 0; j < 8; j++) {
                    int nt = j >> 1, hi = j & 1;
                    MMA16816F16(acc[mt][j], a[mt][0], a[mt][1], a[mt][2], a[mt][3],
                                b[nt][hi], b[nt][hi + 2]);
                }
            }
        }
        __syncthreads();
    }

#pragma unroll
    for (int mt = 0; mt < 4; mt++) {
        int m0 = bm + wm + mt * 16 + (lane >> 2);
        int m1 = m0 + 8;
        float rs0 = rowsum[((m0 & 7) << 8) | (m0 >> 7)];
        float rs1 = rowsum[((m1 & 7) << 8) | (m1 >> 7)];
#pragma unroll
        for (int j = 0; j < 8; j++) {
            int n = bn + wn + j * 8 + (lane & 3) * 2;
            float b0 = bo[n], b1 = bo[n + 1], v0 = bvo[n], v1 = bvo[n + 1];
            *(float2*)(out + (size_t)m0 * 1024 + n) =
                make_float2(acc[mt][j][0] + b0 + rs0 * v0, acc[mt][j][1] + b1 + rs0 * v1);
            *(float2*)(out + (size_t)m1 * 1024 + n) =
                make_float2(acc[mt][j][2] + b0 + rs1 * v0, acc[mt][j][3] + b1 + rs1 * v1);
        }
    }
}

// =================== zmix as fp16 warp-MMA (frozen champion) ===================
#define ZA_ROW_B 80
#define ZA_TILE_B (128*ZA_ROW_B)
#define ZB_ROW_B 272
#define ZB_TILE_B (32*ZB_ROW_B)
#define ZSTAGE_B (ZA_TILE_B + ZB_TILE_B)
#define ZSMEM (2*ZSTAGE_B)

__global__ __launch_bounds__(256, 1)
void zmix_hmma_kernel(const __half* __restrict__ Ph, const __half* __restrict__ Vh,
                      __half* __restrict__ Zh) {
    extern __shared__ char smem[];
    uint32_t sbase = smem_u32(smem);

    int tid = threadIdx.x, wid = tid >> 5, lane = tid & 31;
    int b = blockIdx.z;
    int pos = blockIdx.y >> 1, mt0 = blockIdx.y & 1;
    int bm = mt0 * 128, bn = blockIdx.x * 128;
    int wm = (wid & 1) * 64, wn = (wid >> 1) * 32;

    const __half* Ag = Ph + (size_t)b * (NB * NB) + (size_t)bm * 256;

    float acc[4][4][4];
#pragma unroll
    for (int i = 0; i < 4; i++)
#pragma unroll
        for (int j = 0; j < 4; j++)
#pragma unroll
            for (int r = 0; r < 4; r++) acc[i][j][r] = 0.f;

    auto stage_load = [&](int kt, int buf) {
        int k0 = kt * 32;
        uint32_t base = sbase + buf * ZSTAGE_B;
#pragma unroll
        for (int q = 0; q < 2; q++) {
            int c = tid + q * 256;
            int row = c >> 2, seg = c & 3;
            CP_ASYNC16(base + row * ZA_ROW_B + seg * 16,
                       Ag + (size_t)row * 256 + k0 + seg * 8);
        }
#pragma unroll
        for (int q = 0; q < 2; q++) {
            int c = tid + q * 256;
            int kk = c >> 4, seg = c & 15;
            size_t grow = (size_t)(16 * (k0 + kk) + pos) * (B_DIM * E_DIM) + b * E_DIM + bn;
            CP_ASYNC16(base + ZA_TILE_B + kk * ZB_ROW_B + seg * 16, Vh + grow + seg * 8);
        }
        CP_COMMIT();
    };

    int lrow = lane & 15, lhi = lane >> 4;

    stage_load(0, 0);
    for (int kt = 0; kt < 8; kt++) {
        if (kt + 1 < 8) { stage_load(kt + 1, (kt + 1) & 1); CP_WAIT1(); }
        else CP_WAIT0();
        __syncthreads();

        uint32_t base = sbase + (kt & 1) * ZSTAGE_B;
        uint32_t aS = base, bS = base + ZA_TILE_B;

#pragma unroll
        for (int ks = 0; ks < 2; ks++) {
            uint32_t a[4][4], bt[2][4];
#pragma unroll
            for (int mt = 0; mt < 4; mt++) {
                uint32_t off = (wm + mt * 16 + lrow) * ZA_ROW_B + (ks * 16 + lhi * 8) * 2;
                LDSM_X4(a[mt][0], a[mt][1], a[mt][2], a[mt][3], aS + off);
            }
#pragma unroll
            for (int ng = 0; ng < 2; ng++) {
                uint32_t off = (ks * 16 + lrow) * ZB_ROW_B + (wn + ng * 16 + lhi * 8) * 2;
                LDSM_X4_T(bt[ng][0], bt[ng][1], bt[ng][2], bt[ng][3], bS + off);
            }
#pragma unroll
            for (int mt = 0; mt < 4; mt++) {
#pragma unroll
                for (int j = 0; j < 4; j++) {
                    int ng = j >> 1, hi = j & 1;
                    MMA16816F16(acc[mt][j], a[mt][0], a[mt][1], a[mt][2], a[mt][3],
                                bt[ng][hi * 2], bt[ng][hi * 2 + 1]);
                }
            }
        }
        __syncthreads();
    }

#pragma unroll
    for (int mt = 0; mt < 4; mt++) {
        int tb0 = bm + wm + mt * 16 + (lane >> 2);
        int tb1 = tb0 + 8;
        size_t r0 = ((size_t)(tb0 * 16 + pos) * 8 + b) * 1024;
        size_t r1 = ((size_t)(tb1 * 16 + pos) * 8 + b) * 1024;
#pragma unroll
        for (int j = 0; j < 4; j++) {
            int e = bn + wn + j * 8 + (lane & 3) * 2;
            *(__half2*)(Zh + r0 + e) = __floats2half2_rn(acc[mt][j][0], acc[mt][j][1]);
            *(__half2*)(Zh + r1 + e) = __floats2half2_rn(acc[mt][j][2], acc[mt][j][3]);
        }
    }
}

// =================== elementwise / small kernels ===================
__global__ void bucket_mean_h_kernel(const float* __restrict__ X, __half* __restrict__ out) {
    int o = blockIdx.x * 256 + threadIdx.x;
    int e = o & (E_DIM - 1);
    int m = o >> 10;
    int b = m >> 8;
    int i = m & 255;
    const float* src = X + (size_t)(i * BUCKET) * (B_DIM * E_DIM) + b * E_DIM + e;
    float s = 0.f;
#pragma unroll
    for (int pos = 0; pos < BUCKET; pos++) s += src[(size_t)pos * (B_DIM * E_DIM)];
    out[o] = __float2half_rn(s * (1.0f / BUCKET));
}

__global__ void kpmb_kernel(const unsigned char* __restrict__ mask, int* __restrict__ kpmb) {
    int j = blockIdx.x * 256 + threadIdx.x;
    if (j >= B_DIM * NB) return;
    int b = j >> 8, s = j & 255;
    const unsigned char* m = mask + b * S_DIM + s * BUCKET;
    int all = 1;
#pragma unroll
    for (int t = 0; t < BUCKET; t++) all &= (m[t] != 0);
    kpmb[j] = all;
}

__global__ void bvo_kernel(const float* __restrict__ Wo, const float* __restrict__ bv,
                           float* __restrict__ bvo) {
    int g = blockIdx.x * 8 + (threadIdx.x >> 5);
    int l = threadIdx.x & 31;
    if (g >= E_DIM) return;
    float s = 0.f;
    for (int k = l; k < E_DIM; k += 32) s += Wo[(size_t)g * E_DIM + k] * bv[k];
#pragma unroll
    for (int off = 16; off; off >>= 1) s += __shfl_xor_sync(0xffffffffu, s, off);
    if (l == 0) bvo[g] = s;
}

__global__ void cvt8_kernel(const float* __restrict__ X, __half* __restrict__ H) {
    size_t i = ((size_t)blockIdx.x * 256 + threadIdx.x) * 8;
    float4 a = *(const float4*)(X + i);
    float4 c = *(const float4*)(X + i + 4);
    __half2 h[4];
    h[0] = __floats2half2_rn(a.x, a.y);
    h[1] = __floats2half2_rn(a.z, a.w);
    h[2] = __floats2half2_rn(c.x, c.y);
    h[3] = __floats2half2_rn(c.z, c.w);
    *(uint4*)(H + i) = *(uint4*)h;
}

__global__ void cvt8x4_kernel(const float* __restrict__ W0, const float* __restrict__ W1,
                              const float* __restrict__ W2, const float* __restrict__ W3,
                              __half* __restrict__ H0, __half* __restrict__ H1,
                              __half* __restrict__ H2, __half* __restrict__ H3) {
    const float* X = (blockIdx.y == 0) ? W0 : (blockIdx.y == 1) ? W1 : (blockIdx.y == 2) ? W2 : W3;
    __half* H = (blockIdx.y == 0) ? H0 : (blockIdx.y == 1) ? H1 : (blockIdx.y == 2) ? H2 : H3;
    size_t i = ((size_t)blockIdx.x * 256 + threadIdx.x) * 8;
    float4 a = *(const float4*)(X + i);
    float4 c = *(const float4*)(X + i + 4);
    __half2 h[4];
    h[0] = __floats2half2_rn(a.x, a.y);
    h[1] = __floats2half2_rn(a.z, a.w);
    h[2] = __floats2half2_rn(c.x, c.y);
    h[3] = __floats2half2_rn(c.z, c.w);
    *(uint4*)(H + i) = *(uint4*)h;
}

// ---------------- fused sinkhorn: mask fused; skip row-max for it>=1; exp-reuse ----------------
__global__ __launch_bounds__(1024, 1)
void sinkhorn_kernel(float* __restrict__ la, const int* __restrict__ kpmb,
                     __half* __restrict__ ph, float* __restrict__ rowsum) {
    int b = blockIdx.x;
    float* base = la + b * (NB * NB);
    int tid = threadIdx.x, w = tid >> 5, l = tid & 31;
    __shared__ float sh[32 * 256];
    __shared__ float colv[256];
    __shared__ int mflag[256];
    if (tid < 256) { colv[tid] = 0.f; mflag[tid] = kpmb[b * 256 + tid]; }
    __syncthreads();

    int cf[8];
#pragma unroll
    for (int ci = 0; ci < 8; ci++) cf[ci] = mflag[ci * 32 + l];

    for (int it = 0; it < 8; it++) {
        float cv[8], cs[8];
#pragma unroll
        for (int ci = 0; ci < 8; ci++) { cv[ci] = colv[ci * 32 + l]; cs[ci] = 0.f; }
#pragma unroll
        for (int ri = 0; ri < 8; ri++) {
            int r = w * 8 + ri;
            float v[8];
#pragma unroll
            for (int ci = 0; ci < 8; ci++) v[ci] = base[r * 256 + ci * 32 + l] - cv[ci];
            float m = 0.f;
            if (it == 0) {   // masked first pass: values unbounded -> need max
                int rf = mflag[r];
#pragma unroll
                for (int ci = 0; ci < 8; ci++) if (rf != cf[ci]) v[ci] = -1e30f;
                m = v[0];
#pragma unroll
                for (int ci = 1; ci < 8; ci++) m = fmaxf(m, v[ci]);
#pragma unroll
                for (int off = 16; off; off >>= 1) m = fmaxf(m, __shfl_xor_sync(0xffffffffu, m, off));
            }
            // it>=1: after column normalize, all entries <= 0 -> exp safe without max
            float e[8];
            float s = 0.f;
#pragma unroll
            for (int ci = 0; ci < 8; ci++) { e[ci] = __expf(v[ci] - m); s += e[ci]; }
#pragma unroll
            for (int off = 16; off; off >>= 1) s += __shfl_xor_sync(0xffffffffu, s, off);
            float lse = m + __logf(s);
            float inv = __fdividef(1.0f, s);
#pragma unroll
            for (int ci = 0; ci < 8; ci++) {
                base[r * 256 + ci * 32 + l] = v[ci] - lse;
                cs[ci] += e[ci] * inv;      // == exp(v - lse)
            }
        }
#pragma unroll
        for (int ci = 0; ci < 8; ci++) sh[w * 256 + ci * 32 + l] = cs[ci];
        __syncthreads();
        if (tid < 256) {
            float s = 0.f;
#pragma unroll 4
            for (int ww = 0; ww < 32; ww++) s += sh[ww * 256 + tid];
            colv[tid] = __logf(s);
        }
        __syncthreads();
    }

    float cv[8];
#pragma unroll
    for (int ci = 0; ci < 8; ci++) cv[ci] = colv[ci * 32 + l];
#pragma unroll
    for (int ri = 0; ri < 8; ri++) {
        int r = w * 8 + ri;
        float s = 0.f;
#pragma unroll
        for (int ci = 0; ci < 8; ci++) {
            float e = __expf(base[r * 256 + ci * 32 + l] - cv[ci]);
            ph[b * (NB * NB) + r * 256 + ci * 32 + l] = __float2half_rn(e);
            s += e;
        }
#pragma unroll
        for (int off = 16; off; off >>= 1) s += __shfl_xor_sync(0xffffffffu, s, off);
        if (l == 0) rowsum[b * 256 + r] = s;
    }
}

// ---------------- launch ----------------
extern "C" void kernel_launch(void* const* d_in, const int* in_sizes, int n_in,
                              void* d_out, int out_size) {
    const float* query = (const float*)d_in[0];
    const float* key_t = (const float*)d_in[1];
    const float* value = (const float*)d_in[2];
    const unsigned char* kpm = (const unsigned char*)d_in[3];
    const float* Wq = (const float*)d_in[4];
    const float* bq = (const float*)d_in[5];
    const float* Wk = (const float*)d_in[6];
    const float* bk = (const float*)d_in[7];
    const float* Wv = (const float*)d_in[8];
    const float* bv = (const float*)d_in[9];
    const float* Wo = (const float*)d_in[10];
    const float* bo = (const float*)d_in[11];
    float* out = (float*)d_out;

    float *la, *rowsum, *bvo, *bqk;
    __half *qkmh, *qkbh, *Wqkh, *Wvh, *Woh, *ph, *vh, *zh, *wvoh;
    int* kpmb;
    cudaGetSymbolAddress((void**)&qkmh, g_qkmh);
    cudaGetSymbolAddress((void**)&qkbh, g_qkbh);
    cudaGetSymbolAddress((void**)&Wqkh, g_Wqkh);
    cudaGetSymbolAddress((void**)&Wvh, g_Wvh);
    cudaGetSymbolAddress((void**)&Woh, g_Woh);
    cudaGetSymbolAddress((void**)&bqk, g_bqk);
    cudaGetSymbolAddress((void**)&la, g_la);
    cudaGetSymbolAddress((void**)&ph, g_ph);
    cudaGetSymbolAddress((void**)&rowsum, g_rowsum);
    cudaGetSymbolAddress((void**)&kpmb, g_kpmb);
    cudaGetSymbolAddress((void**)&bvo, g_bvo);
    cudaGetSymbolAddress((void**)&vh, g_vh);
    cudaGetSymbolAddress((void**)&zh, g_zh);
    cudaGetSymbolAddress((void**)&wvoh, g_wvoh);

    static bool attr_set = false;
    if (!attr_set) {
        cudaFuncSetAttribute(hmma_out_kernel, cudaFuncAttributeMaxDynamicSharedMemorySize, HMMA_SMEM);
        attr_set = true;
    }

    const int HG_SMEM_N = 2 * (HG_A_TILE + HG_A_TILE);   // 40960
    const int HG_SMEM_T = 2 * (HG_A_TILE + HG_BT_TILE);  // 37888
    const int EE = E_DIM * E_DIM;

    // 0) conversions + bias pack + la zero (all independent, front of graph)
    cvt8_kernel<<<(S_DIM * B_DIM * E_DIM) / 2048, 256>>>(value, vh);
    cvt8x4_kernel<<<dim3(EE / 2048, 4), 256>>>(Wq, Wk, Wv, Wo,
                                               Wqkh, Wqkh + EE, Wvh, Woh);
    cudaMemcpyAsync(bqk, bq, E_DIM * sizeof(float), cudaMemcpyDeviceToDevice);
    cudaMemcpyAsync(bqk + E_DIM, bk, E_DIM * sizeof(float), cudaMemcpyDeviceToDevice);
    cudaMemsetAsync(la, 0, (size_t)B_DIM * NB * NB * sizeof(float));
    kpmb_kernel<<<8, 256>>>(kpm, kpmb);

    // 1) bucket means -> fp16 (q | k halves of qkmh)
    bucket_mean_h_kernel<<<(B_DIM * NB * E_DIM) / 256, 256>>>(query, qkmh);
    bucket_mean_h_kernel<<<(B_DIM * NB * E_DIM) / 256, 256>>>(key_t, qkmh + QK_STRIDE);

    // 2) batched Q+K projection: one launch, 256 CTAs (full chip)
    hgemm_kernel<false, true, true, false><<<dim3(8, 16, 2), 256, HG_SMEM_N>>>(
        qkbh, qkmh, Wqkh, bqk, 2048, 1024, 1024, 1024, 1.0f,
        (long)QK_STRIDE, (long)EE, (long)QK_STRIDE);

    // 3) wvo = Wo @ Wv (B trans), fp16 out; bvo = Wo @ bv (fp32)
    hgemm_kernel<true, false, true, false><<<dim3(8, 8, 1), 256, HG_SMEM_T>>>(
        wvoh, Woh, Wvh, nullptr, 1024, 1024, 1024, 1024, 1.0f, 0, 0, 0);
    bvo_kernel<<<128, 256>>>(Wo, bv, bvo);

    // 4) attn logits: split-K x2 (64 CTAs), fp32 atomicAdd into zeroed la
    hgemm_kernel<false, false, false, true><<<dim3(2, 2, 2 * B_DIM), 256, HG_SMEM_N>>>(
        la, qkbh, qkbh + QK_STRIDE, nullptr, 256, 256, 512, 1024, ATTN_ALPHA,
        (long)NB * E_DIM, (long)NB * E_DIM, (long)NB * NB);

    // 5) sinkhorn (mask fused) -> ph (fp16), rowsum
    sinkhorn_kernel<<<B_DIM, 1024>>>(la, kpmb, ph, rowsum);

    // 6) bucket mix via fp16 MMA -> zh
    zmix_hmma_kernel<<<dim3(8, 32, 8), 256, ZSMEM>>>(ph, vh, zh);

    // 7) final: fp16 warp-MMA GEMM (M=32768, N=1024, K=1024)
    hmma_out_kernel<<<dim3(4, 256, 1), 256, HMMA_SMEM>>>(
        out, zh, wvoh, bo, bvo, rowsum);
}

// round 14
// speedup vs baseline: 1.0333x; 1.0333x over previous
#include <cuda_runtime.h>
#include <cuda_bf16.h>
#include <cuda_fp16.h>
#include <math.h>
#include <cstdint>

// ---------------- problem constants ----------------
#define T_DIM 4096
#define S_DIM 4096
#define B_DIM 8
#define E_DIM 1024
#define BUCKET 16
#define NB 256            // T/BUCKET
#define TAU 0.75f
#define ATTN_ALPHA (1.0f/(32.0f*0.75f))
#define QK_STRIDE (B_DIM*NB*E_DIM)   // 2097152

// ---------------- scratch (device globals; no allocation allowed) ----------------
__device__ __half g_qkmh[2*QK_STRIDE];      // bucket means q|k, fp16
__device__ __half g_qkbh[2*QK_STRIDE];      // projected bucket q|k, fp16
__device__ __half g_Wqkh[2*E_DIM*E_DIM];    // Wq|Wk fp16
__device__ __half g_Wvh[E_DIM*E_DIM];
__device__ __half g_Woh[E_DIM*E_DIM];
__device__ float g_bqk[2*E_DIM];            // bq|bk fp32
__device__ float g_la[B_DIM*NB*NB];
__device__ __half g_ph[B_DIM*NB*NB];        // sinkhorn result, fp16
__device__ float g_rowsum[B_DIM*NB];
__device__ int   g_kpmb[B_DIM*NB];
__device__ float g_bvo[E_DIM];              // Wo @ bv
__device__ __half g_vh[S_DIM*B_DIM*E_DIM];  // value in fp16
__device__ __half g_zh[T_DIM*B_DIM*E_DIM];  // mixed value, fp16 (rows m=t*8+b)
__device__ __half g_wvoh[E_DIM*E_DIM];      // Wo @ Wv in fp16

// =================== warp-MMA helpers (compute_80-compatible PTX) ===================
__device__ __forceinline__ uint32_t smem_u32(const void* p) {
    uint32_t a;
    asm("{ .reg .u64 t; cvta.to.shared.u64 t, %1; cvt.u32.u64 %0, t; }" : "=r"(a) : "l"(p));
    return a;
}

#define CP_ASYNC16(dst, src) \
    asm volatile("cp.async.cg.shared.global [%0], [%1], 16;" :: "r"(dst), "l"(src))
#define CP_COMMIT() asm volatile("cp.async.commit_group;")
#define CP_WAIT3()  asm volatile("cp.async.wait_group 3;")
#define CP_WAIT1()  asm volatile("cp.async.wait_group 1;")
#define CP_WAIT0()  asm volatile("cp.async.wait_group 0;")

#define LDSM_X4(r0, r1, r2, r3, addr) \
    asm volatile("ldmatrix.sync.aligned.m8n8.x4.shared.b16 {%0,%1,%2,%3}, [%4];" \
        : "=r"(r0), "=r"(r1), "=r"(r2), "=r"(r3) : "r"(addr))

#define LDSM_X4_T(r0, r1, r2, r3, addr) \
    asm volatile("ldmatrix.sync.aligned.m8n8.x4.trans.shared.b16 {%0,%1,%2,%3}, [%4];" \
        : "=r"(r0), "=r"(r1), "=r"(r2), "=r"(r3) : "r"(addr))

#define MMA16816F16(d, a0, a1, a2, a3, b0, b1) \
    asm volatile("mma.sync.aligned.m16n8k16.row.col.f32.f16.f16.f32 " \
        "{%0,%1,%2,%3}, {%4,%5,%6,%7}, {%8,%9}, {%0,%1,%2,%3};" \
        : "+f"((d)[0]), "+f"((d)[1]), "+f"((d)[2]), "+f"((d)[3]) \
        : "r"(a0), "r"(a1), "r"(a2), "r"(a3), "r"(b0), "r"(b1))

// =================== generic fp16 HMMA GEMM (frozen core) ===================
#define HG_A_ROW 80
#define HG_A_TILE (128*HG_A_ROW)   // 10240
#define HG_BT_ROW 272
#define HG_BT_TILE (32*HG_BT_ROW)  // 8704

template <bool BTRANS, bool BIAS, bool OUT_HALF, bool SPLITK>
__global__ __launch_bounds__(256)
void hgemm_kernel(void* __restrict__ Cv, const __half* __restrict__ A,
                  const __half* __restrict__ B, const float* __restrict__ bias,
                  int M, int N, int K, int lda, float alpha, long sA, long sB, long sC) {
    constexpr int B_TILE = BTRANS ? HG_BT_TILE : HG_A_TILE;
    constexpr int STAGE = HG_A_TILE + B_TILE;
    extern __shared__ char smem[];
    uint32_t sbase = smem_u32(smem);

    int z = blockIdx.z;
    long cofs;
    if (SPLITK) {
        int zb = z >> 1, zs = z & 1;
        A += (long)zb * sA + zs * K;
        B += (long)zb * sB + zs * K;
        cofs = (long)zb * sC;
    } else {
        A += (long)z * sA; B += (long)z * sB;
        cofs = (long)z * sC;
    }

    int tid = threadIdx.x, wid = tid >> 5, lane = tid & 31;
    int bm = blockIdx.y * 128, bn = blockIdx.x * 128;
    int wm = (wid & 1) * 64, wn = (wid >> 1) * 32;

    float acc[4][4][4];
#pragma unroll
    for (int i = 0; i < 4; i++)
#pragma unroll
        for (int j = 0; j < 4; j++)
#pragma unroll
            for (int r = 0; r < 4; r++) acc[i][j][r] = 0.f;

    auto stage_load = [&](int kt, int buf) {
        int k0 = kt * 32;
        uint32_t base = sbase + buf * STAGE;
#pragma unroll
        for (int q = 0; q < 2; q++) {
            int c = tid + q * 256;
            int row = c >> 2, seg = c & 3;
            CP_ASYNC16(base + row * HG_A_ROW + seg * 16,
                       A + (size_t)(bm + row) * lda + k0 + seg * 8);
        }
        if (!BTRANS) {
#pragma unroll
            for (int q = 0; q < 2; q++) {
                int c = tid + q * 256;
                int row = c >> 2, seg = c & 3;
                CP_ASYNC16(base + HG_A_TILE + row * HG_A_ROW + seg * 16,
                           B + (size_t)(bn + row) * lda + k0 + seg * 8);
            }
        } else {
#pragma unroll
            for (int q = 0; q < 2; q++) {
                int c = tid + q * 256;
                int kk = c >> 4, seg = c & 15;
                CP_ASYNC16(base + HG_A_TILE + kk * HG_BT_ROW + seg * 16,
                           B + (size_t)(k0 + kk) * N + bn + seg * 8);
            }
        }
        CP_COMMIT();
    };

    int lrow = lane & 15, lhi = lane >> 4;

    stage_load(0, 0);
    int NKT = K / 32;
    for (int kt = 0; kt < NKT; kt++) {
        if (kt + 1 < NKT) { stage_load(kt + 1, (kt + 1) & 1); CP_WAIT1(); }
        else CP_WAIT0();
        __syncthreads();

        uint32_t base = sbase + (kt & 1) * STAGE;
        uint32_t aS = base, bS = base + HG_A_TILE;

#pragma unroll
        for (int ks = 0; ks < 2; ks++) {
            uint32_t a[4][4], bt[2][4];
#pragma unroll
            for (int mt = 0; mt < 4; mt++) {
                uint32_t off = (wm + mt * 16 + lrow) * HG_A_ROW + (ks * 16 + lhi * 8) * 2;
                LDSM_X4(a[mt][0], a[mt][1], a[mt][2], a[mt][3], aS + off);
            }
            if (!BTRANS) {
#pragma unroll
                for (int nt = 0; nt < 2; nt++) {
                    uint32_t off = (wn + nt * 16 + lrow) * HG_A_ROW + (ks * 16 + lhi * 8) * 2;
                    LDSM_X4(bt[nt][0], bt[nt][1], bt[nt][2], bt[nt][3], bS + off);
                }
#pragma unroll
                for (int mt = 0; mt < 4; mt++)
#pragma unroll
                    for (int j = 0; j < 4; j++) {
                        int nt = j >> 1, hi = j & 1;
                        MMA16816F16(acc[mt][j], a[mt][0], a[mt][1], a[mt][2], a[mt][3],
                                    bt[nt][hi], bt[nt][hi + 2]);
                    }
            } else {
#pragma unroll
                for (int ng = 0; ng < 2; ng++) {
                    uint32_t off = (ks * 16 + lrow) * HG_BT_ROW + (wn + ng * 16 + lhi * 8) * 2;
                    LDSM_X4_T(bt[ng][0], bt[ng][1], bt[ng][2], bt[ng][3], bS + off);
                }
#pragma unroll
                for (int mt = 0; mt < 4; mt++)
#pragma unroll
                    for (int j = 0; j < 4; j++) {
                        int ng = j >> 1, hi = j & 1;
                        MMA16816F16(acc[mt][j], a[mt][0], a[mt][1], a[mt][2], a[mt][3],
                                    bt[ng][hi * 2], bt[ng][hi * 2 + 1]);
                    }
            }
        }
        __syncthreads();
    }

    // ---- epilogue ----
#pragma unroll
    for (int mt = 0; mt < 4; mt++) {
        int m0 = bm + wm + mt * 16 + (lane >> 2);
        int m1 = m0 + 8;
#pragma unroll
        for (int j = 0; j < 4; j++) {
            int n = bn + wn + j * 8 + (lane & 3) * 2;
            float v00 = acc[mt][j][0] * alpha, v01 = acc[mt][j][1] * alpha;
            float v10 = acc[mt][j][2] * alpha, v11 = acc[mt][j][3] * alpha;
            if (BIAS) {
                float b0 = bias[(long)blockIdx.z * N + n], b1 = bias[(long)blockIdx.z * N + n + 1];
                v00 += b0; v01 += b1; v10 += b0; v11 += b1;
            }
            if (SPLITK) {
                float* C = (float*)Cv + cofs;
                atomicAdd(C + (size_t)m0 * N + n, v00);
                atomicAdd(C + (size_t)m0 * N + n + 1, v01);
                atomicAdd(C + (size_t)m1 * N + n, v10);
                atomicAdd(C + (size_t)m1 * N + n + 1, v11);
            } else if (OUT_HALF) {
                __half* C = (__half*)Cv + cofs;
                *(__half2*)(C + (size_t)m0 * N + n) = __floats2half2_rn(v00, v01);
                *(__half2*)(C + (size_t)m1 * N + n) = __floats2half2_rn(v10, v11);
            } else {
                float* C = (float*)Cv + cofs;
                *(float2*)(C + (size_t)m0 * N + n) = make_float2(v00, v01);
                *(float2*)(C + (size_t)m1 * N + n) = make_float2(v10, v11);
            }
        }
    }
}

// =================== final GEMM (frozen champion config) ===================
#define KC 32
#define ROW_B 80
#define A_TILE_B (128*ROW_B)
#define B_TILE_B (256*ROW_B)
#define STAGE_B (A_TILE_B + B_TILE_B)
#define HMMA_SMEM (4*STAGE_B)

__global__ __launch_bounds__(256, 1)
void hmma_out_kernel(float* __restrict__ out,
                     const __half* __restrict__ Ah, const __half* __restrict__ Bh,
                     const float* __restrict__ bo, const float* __restrict__ bvo,
                     const float* __restrict__ rowsum) {
    extern __shared__ char smem[];
    uint32_t sbase = smem_u32(smem);

    int tid = threadIdx.x, wid = tid >> 5, lane = tid & 31;
    int bm = blockIdx.y * 128, bn = blockIdx.x * 256;
    int wm = (wid & 1) * 64, wn = (wid >> 1) * 64;

    const __half* Ag = Ah + (size_t)bm * 1024;
    const __half* Bg = Bh + (size_t)bn * 1024;

    float acc[4][8][4];
#pragma unroll
    for (int i = 0; i < 4; i++)
#pragma unroll
        for (int j = 0; j < 8; j++)
#pragma unroll
            for (int r = 0; r < 4; r++) acc[i][j][r] = 0.f;

    auto stage_load = [&](int kt, int buf) {
        int k0 = kt * KC;
        uint32_t base = sbase + buf * STAGE_B;
#pragma unroll
        for (int q = 0; q < 2; q++) {
            int c = tid + q * 256;
            int row = c >> 2, seg = c & 3;
            CP_ASYNC16(base + row * ROW_B + seg * 16,
                       Ag + (size_t)row * 1024 + k0 + seg * 8);
        }
#pragma unroll
        for (int q = 0; q < 4; q++) {
            int c = tid + q * 256;
            int row = c >> 2, seg = c & 3;
            CP_ASYNC16(base + A_TILE_B + row * ROW_B + seg * 16,
                       Bg + (size_t)row * 1024 + k0 + seg * 8);
        }
    };

    int lrow = lane & 15, lkseg = (lane >> 4) * 8;

    stage_load(0, 0); CP_COMMIT();
    stage_load(1, 1); CP_COMMIT();
    stage_load(2, 2); CP_COMMIT();

    const int NKT = 1024 / KC;
    for (int kt = 0; kt < NKT; kt++) {
        if (kt + 3 < NKT) stage_load(kt + 3, (kt + 3) & 3);
        CP_COMMIT();
        CP_WAIT3();
        __syncthreads();

        uint32_t base = sbase + (kt & 3) * STAGE_B;
        uint32_t aS = base, bS = base + A_TILE_B;

#pragma unroll
        for (int ks = 0; ks < KC / 16; ks++) {
            int kb = (ks * 16 + lkseg) * 2;
            uint32_t a[4][4], b[4][4];
#pragma unroll
            for (int mt = 0; mt < 4; mt++) {
                uint32_t off = (wm + mt * 16 + lrow) * ROW_B + kb;
                LDSM_X4(a[mt][0], a[mt][1], a[mt][2], a[mt][3], aS + off);
            }
#pragma unroll
            for (int nt = 0; nt < 4; nt++) {
                uint32_t off = (wn + nt * 16 + lrow) * ROW_B + kb;
                LDSM_X4(b[nt][0], b[nt][1], b[nt][2], b[nt][3], bS + off);
            }
#pragma unroll
            for (int mt = 0; mt < 4; mt++) {
#pragma unroll
                for (int j = 0; j < 8; j++) {
                    int nt = j >> 1, hi = j & 1;
                    MMA16816F16(acc[mt][j], a[mt][0], a[mt][1], a[mt][2], a[mt][3],
                                b[nt][hi], b[nt][hi + 2]);
                }
            }
        }
        __syncthreads();
    }

#pragma unroll
    for (int mt = 0; mt < 4; mt++) {
        int m0 = bm + wm + mt * 16 + (lane >> 2);
        int m1 = m0 + 8;
        float rs0 = rowsum[((m0 & 7) << 8) | (m0 >> 7)];
        float rs1 = rowsum[((m1 & 7) << 8) | (m1 >> 7)];
#pragma unroll
        for (int j = 0; j < 8; j++) {
            int n = bn + wn + j * 8 + (lane & 3) * 2;
            float b0 = bo[n], b1 = bo[n + 1], v0 = bvo[n], v1 = bvo[n + 1];
            *(float2*)(out + (size_t)m0 * 1024 + n) =
                make_float2(acc[mt][j][0] + b0 + rs0 * v0, acc[mt][j][1] + b1 + rs0 * v1);
            *(float2*)(out + (size_t)m1 * 1024 + n) =
                make_float2(acc[mt][j][2] + b0 + rs1 * v0, acc[mt][j][3] + b1 + rs1 * v1);
        }
    }
}

// =================== zmix as fp16 warp-MMA (frozen champion) ===================
#define ZA_ROW_B 80
#define ZA_TILE_B (128*ZA_ROW_B)
#define ZB_ROW_B 272
#define ZB_TILE_B (32*ZB_ROW_B)
#define ZSTAGE_B (ZA_TILE_B + ZB_TILE_B)
#define ZSMEM (2*ZSTAGE_B)

__global__ __launch_bounds__(256, 1)
void zmix_hmma_kernel(const __half* __restrict__ Ph, const __half* __restrict__ Vh,
                      __half* __restrict__ Zh) {
    extern __shared__ char smem[];
    uint32_t sbase = smem_u32(smem);

    int tid = threadIdx.x, wid = tid >> 5, lane = tid & 31;
    int b = blockIdx.z;
    int pos = blockIdx.y >> 1, mt0 = blockIdx.y & 1;
    int bm = mt0 * 128, bn = blockIdx.x * 128;
    int wm = (wid & 1) * 64, wn = (wid >> 1) * 32;

    const __half* Ag = Ph + (size_t)b * (NB * NB) + (size_t)bm * 256;

    float acc[4][4][4];
#pragma unroll
    for (int i = 0; i < 4; i++)
#pragma unroll
        for (int j = 0; j < 4; j++)
#pragma unroll
            for (int r = 0; r < 4; r++) acc[i][j][r] = 0.f;

    auto stage_load = [&](int kt, int buf) {
        int k0 = kt * 32;
        uint32_t base = sbase + buf * ZSTAGE_B;
#pragma unroll
        for (int q = 0; q < 2; q++) {
            int c = tid + q * 256;
            int row = c >> 2, seg = c & 3;
            CP_ASYNC16(base + row * ZA_ROW_B + seg * 16,
                       Ag + (size_t)row * 256 + k0 + seg * 8);
        }
#pragma unroll
        for (int q = 0; q < 2; q++) {
            int c = tid + q * 256;
            int kk = c >> 4, seg = c & 15;
            size_t grow = (size_t)(16 * (k0 + kk) + pos) * (B_DIM * E_DIM) + b * E_DIM + bn;
            CP_ASYNC16(base + ZA_TILE_B + kk * ZB_ROW_B + seg * 16, Vh + grow + seg * 8);
        }
        CP_COMMIT();
    };

    int lrow = lane & 15, lhi = lane >> 4;

    stage_load(0, 0);
    for (int kt = 0; kt < 8; kt++) {
        if (kt + 1 < 8) { stage_load(kt + 1, (kt + 1) & 1); CP_WAIT1(); }
        else CP_WAIT0();
        __syncthreads();

        uint32_t base = sbase + (kt & 1) * ZSTAGE_B;
        uint32_t aS = base, bS = base + ZA_TILE_B;

#pragma unroll
        for (int ks = 0; ks < 2; ks++) {
            uint32_t a[4][4], bt[2][4];
#pragma unroll
            for (int mt = 0; mt < 4; mt++) {
                uint32_t off = (wm + mt * 16 + lrow) * ZA_ROW_B + (ks * 16 + lhi * 8) * 2;
                LDSM_X4(a[mt][0], a[mt][1], a[mt][2], a[mt][3], aS + off);
            }
#pragma unroll
            for (int ng = 0; ng < 2; ng++) {
                uint32_t off = (ks * 16 + lrow) * ZB_ROW_B + (wn + ng * 16 + lhi * 8) * 2;
                LDSM_X4_T(bt[ng][0], bt[ng][1], bt[ng][2], bt[ng][3], bS + off);
            }
#pragma unroll
            for (int mt = 0; mt < 4; mt++) {
#pragma unroll
                for (int j = 0; j < 4; j++) {
                    int ng = j >> 1, hi = j & 1;
                    MMA16816F16(acc[mt][j], a[mt][0], a[mt][1], a[mt][2], a[mt][3],
                                bt[ng][hi * 2], bt[ng][hi * 2 + 1]);
                }
            }
        }
        __syncthreads();
    }

#pragma unroll
    for (int mt = 0; mt < 4; mt++) {
        int tb0 = bm + wm + mt * 16 + (lane >> 2);
        int tb1 = tb0 + 8;
        size_t r0 = ((size_t)(tb0 * 16 + pos) * 8 + b) * 1024;
        size_t r1 = ((size_t)(tb1 * 16 + pos) * 8 + b) * 1024;
#pragma unroll
        for (int j = 0; j < 4; j++) {
            int e = bn + wn + j * 8 + (lane & 3) * 2;
            *(__half2*)(Zh + r0 + e) = __floats2half2_rn(acc[mt][j][0], acc[mt][j][1]);
            *(__half2*)(Zh + r1 + e) = __floats2half2_rn(acc[mt][j][2], acc[mt][j][3]);
        }
    }
}

// =================== elementwise / small kernels ===================
__global__ void bucket_mean_h_kernel(const float* __restrict__ X, __half* __restrict__ out) {
    int o = blockIdx.x * 256 + threadIdx.x;
    int e = o & (E_DIM - 1);
    int m = o >> 10;
    int b = m >> 8;
    int i = m & 255;
    const float* src = X + (size_t)(i * BUCKET) * (B_DIM * E_DIM) + b * E_DIM + e;
    float s = 0.f;
#pragma unroll
    for (int pos = 0; pos < BUCKET; pos++) s += src[(size_t)pos * (B_DIM * E_DIM)];
    out[o] = __float2half_rn(s * (1.0f / BUCKET));
}

__global__ void kpmb_kernel(const unsigned char* __restrict__ mask, int* __restrict__ kpmb) {
    int j = blockIdx.x * 256 + threadIdx.x;
    if (j >= B_DIM * NB) return;
    int b = j >> 8, s = j & 255;
    const unsigned char* m = mask + b * S_DIM + s * BUCKET;
    int all = 1;
#pragma unroll
    for (int t = 0; t < BUCKET; t++) all &= (m[t] != 0);
    kpmb[j] = all;
}

__global__ void bvo_kernel(const float* __restrict__ Wo, const float* __restrict__ bv,
                           float* __restrict__ bvo) {
    int g = blockIdx.x * 8 + (threadIdx.x >> 5);
    int l = threadIdx.x & 31;
    if (g >= E_DIM) return;
    float s = 0.f;
    for (int k = l; k < E_DIM; k += 32) s += Wo[(size_t)g * E_DIM + k] * bv[k];
#pragma unroll
    for (int off = 16; off; off >>= 1) s += __shfl_xor_sync(0xffffffffu, s, off);
    if (l == 0) bvo[g] = s;
}

__global__ void cvt8_kernel(const float* __restrict__ X, __half* __restrict__ H) {
    size_t i = ((size_t)blockIdx.x * 256 + threadIdx.x) * 8;
    float4 a = *(const float4*)(X + i);
    float4 c = *(const float4*)(X + i + 4);
    __half2 h[4];
    h[0] = __floats2half2_rn(a.x, a.y);
    h[1] = __floats2half2_rn(a.z, a.w);
    h[2] = __floats2half2_rn(c.x, c.y);
    h[3] = __floats2half2_rn(c.z, c.w);
    *(uint4*)(H + i) = *(uint4*)h;
}

__global__ void cvt8x4_kernel(const float* __restrict__ W0, const float* __restrict__ W1,
                              const float* __restrict__ W2, const float* __restrict__ W3,
                              __half* __restrict__ H0, __half* __restrict__ H1,
                              __half* __restrict__ H2, __half* __restrict__ H3) {
    const float* X = (blockIdx.y == 0) ? W0 : (blockIdx.y == 1) ? W1 : (blockIdx.y == 2) ? W2 : W3;
    __half* H = (blockIdx.y == 0) ? H0 : (blockIdx.y == 1) ? H1 : (blockIdx.y == 2) ? H2 : H3;
    size_t i = ((size_t)blockIdx.x * 256 + threadIdx.x) * 8;
    float4 a = *(const float4*)(X + i);
    float4 c = *(const float4*)(X + i + 4);
    __half2 h[4];
    h[0] = __floats2half2_rn(a.x, a.y);
    h[1] = __floats2half2_rn(a.z, a.w);
    h[2] = __floats2half2_rn(c.x, c.y);
    h[3] = __floats2half2_rn(c.z, c.w);
    *(uint4*)(H + i) = *(uint4*)h;
}

// ---------------- fused sinkhorn (R13 version) ----------------
__global__ __launch_bounds__(1024, 1)
void sinkhorn_kernel(float* __restrict__ la, const int* __restrict__ kpmb,
                     __half* __restrict__ ph, float* __restrict__ rowsum) {
    int b = blockIdx.x;
    float* base = la + b * (NB * NB);
    int tid = threadIdx.x, w = tid >> 5, l = tid & 31;
    __shared__ float sh[32 * 256];
    __shared__ float colv[256];
    __shared__ int mflag[256];
    if (tid < 256) { colv[tid] = 0.f; mflag[tid] = kpmb[b * 256 + tid]; }
    __syncthreads();

    int cf[8];
#pragma unroll
    for (int ci = 0; ci < 8; ci++) cf[ci] = mflag[ci * 32 + l];

    for (int it = 0; it < 8; it++) {
        float cv[8], cs[8];
#pragma unroll
        for (int ci = 0; ci < 8; ci++) { cv[ci] = colv[ci * 32 + l]; cs[ci] = 0.f; }
#pragma unroll
        for (int ri = 0; ri < 8; ri++) {
            int r = w * 8 + ri;
            float v[8];
#pragma unroll
            for (int ci = 0; ci < 8; ci++) v[ci] = base[r * 256 + ci * 32 + l] - cv[ci];
            float m = 0.f;
            if (it == 0) {
                int rf = mflag[r];
#pragma unroll
                for (int ci = 0; ci < 8; ci++) if (rf != cf[ci]) v[ci] = -1e30f;
                m = v[0];
#pragma unroll
                for (int ci = 1; ci < 8; ci++) m = fmaxf(m, v[ci]);
#pragma unroll
                for (int off = 16; off; off >>= 1) m = fmaxf(m, __shfl_xor_sync(0xffffffffu, m, off));
            }
            float e[8];
            float s = 0.f;
#pragma unroll
            for (int ci = 0; ci < 8; ci++) { e[ci] = __expf(v[ci] - m); s += e[ci]; }
#pragma unroll
            for (int off = 16; off; off >>= 1) s += __shfl_xor_sync(0xffffffffu, s, off);
            float lse = m + __logf(s);
            float inv = __fdividef(1.0f, s);
#pragma unroll
            for (int ci = 0; ci < 8; ci++) {
                base[r * 256 + ci * 32 + l] = v[ci] - lse;
                cs[ci] += e[ci] * inv;
            }
        }
#pragma unroll
        for (int ci = 0; ci < 8; ci++) sh[w * 256 + ci * 32 + l] = cs[ci];
        __syncthreads();
        if (tid < 256) {
            float s = 0.f;
#pragma unroll 4
            for (int ww = 0; ww < 32; ww++) s += sh[ww * 256 + tid];
            colv[tid] = __logf(s);
        }
        __syncthreads();
    }

    float cv[8];
#pragma unroll
    for (int ci = 0; ci < 8; ci++) cv[ci] = colv[ci * 32 + l];
#pragma unroll
    for (int ri = 0; ri < 8; ri++) {
        int r = w * 8 + ri;
        float s = 0.f;
#pragma unroll
        for (int ci = 0; ci < 8; ci++) {
            float e = __expf(base[r * 256 + ci * 32 + l] - cv[ci]);
            ph[b * (NB * NB) + r * 256 + ci * 32 + l] = __float2half_rn(e);
            s += e;
        }
#pragma unroll
        for (int off = 16; off; off >>= 1) s += __shfl_xor_sync(0xffffffffu, s, off);
        if (l == 0) rowsum[b * 256 + r] = s;
    }
}

// ---------------- launch (multi-stream fork/join, capturable) ----------------
extern "C" void kernel_launch(void* const* d_in, const int* in_sizes, int n_in,
                              void* d_out, int out_size) {
    const float* query = (const float*)d_in[0];
    const float* key_t = (const float*)d_in[1];
    const float* value = (const float*)d_in[2];
    const unsigned char* kpm = (const unsigned char*)d_in[3];
    const float* Wq = (const float*)d_in[4];
    const float* bq = (const float*)d_in[5];
    const float* Wk = (const float*)d_in[6];
    const float* bk = (const float*)d_in[7];
    const float* Wv = (const float*)d_in[8];
    const float* bv = (const float*)d_in[9];
    const float* Wo = (const float*)d_in[10];
    const float* bo = (const float*)d_in[11];
    float* out = (float*)d_out;

    float *la, *rowsum, *bvo, *bqk;
    __half *qkmh, *qkbh, *Wqkh, *Wvh, *Woh, *ph, *vh, *zh, *wvoh;
    int* kpmb;
    cudaGetSymbolAddress((void**)&qkmh, g_qkmh);
    cudaGetSymbolAddress((void**)&qkbh, g_qkbh);
    cudaGetSymbolAddress((void**)&Wqkh, g_Wqkh);
    cudaGetSymbolAddress((void**)&Wvh, g_Wvh);
    cudaGetSymbolAddress((void**)&Woh, g_Woh);
    cudaGetSymbolAddress((void**)&bqk, g_bqk);
    cudaGetSymbolAddress((void**)&la, g_la);
    cudaGetSymbolAddress((void**)&ph, g_ph);
    cudaGetSymbolAddress((void**)&rowsum, g_rowsum);
    cudaGetSymbolAddress((void**)&kpmb, g_kpmb);
    cudaGetSymbolAddress((void**)&bvo, g_bvo);
    cudaGetSymbolAddress((void**)&vh, g_vh);
    cudaGetSymbolAddress((void**)&zh, g_zh);
    cudaGetSymbolAddress((void**)&wvoh, g_wvoh);

    // One-time setup on the (uncaptured) correctness call: streams + events.
    static cudaStream_t s1 = nullptr, s2 = nullptr;
    static cudaEvent_t evRoot, evW, evV, evSide;
    static bool init_done = false;
    if (!init_done) {
        cudaFuncSetAttribute(hmma_out_kernel, cudaFuncAttributeMaxDynamicSharedMemorySize, HMMA_SMEM);
        cudaStreamCreateWithFlags(&s1, cudaStreamNonBlocking);
        cudaStreamCreateWithFlags(&s2, cudaStreamNonBlocking);
        cudaEventCreateWithFlags(&evRoot, cudaEventDisableTiming);
        cudaEventCreateWithFlags(&evW, cudaEventDisableTiming);
        cudaEventCreateWithFlags(&evV, cudaEventDisableTiming);
        cudaEventCreateWithFlags(&evSide, cudaEventDisableTiming);
        init_done = true;
    }

    const int HG_SMEM_N = 2 * (HG_A_TILE + HG_A_TILE);   // 40960
    const int HG_SMEM_T = 2 * (HG_A_TILE + HG_BT_TILE);  // 37888
    const int EE = E_DIM * E_DIM;

    // ---- fork side streams off the main (capture) stream ----
    cudaEventRecord(evRoot, 0);
    cudaStreamWaitEvent(s1, evRoot, 0);
    cudaStreamWaitEvent(s2, evRoot, 0);

    // s1: value -> fp16 (consumed only by zmix)
    cvt8_kernel<<<(S_DIM * B_DIM * E_DIM) / 2048, 256, 0, s1>>>(value, vh);
    cudaEventRecord(evV, s1);

    // s2: weight converts -> (evW for qkproj) -> wvo + bvo (consumed by hmma_out)
    cvt8x4_kernel<<<dim3(EE / 2048, 4), 256, 0, s2>>>(Wq, Wk, Wv, Wo,
                                                      Wqkh, Wqkh + EE, Wvh, Woh);
    cudaEventRecord(evW, s2);
    hgemm_kernel<true, false, true, false><<<dim3(8, 8, 1), 256, HG_SMEM_T, s2>>>(
        wvoh, Woh, Wvh, nullptr, 1024, 1024, 1024, 1024, 1.0f, 0, 0, 0);
    bvo_kernel<<<128, 256, 0, s2>>>(Wo, bv, bvo);
    cudaEventRecord(evSide, s2);

    // main stream: bias pack, la zero, mask flags, bucket means
    cudaMemcpyAsync(bqk, bq, E_DIM * sizeof(float), cudaMemcpyDeviceToDevice, 0);
    cudaMemcpyAsync(bqk + E_DIM, bk, E_DIM * sizeof(float), cudaMemcpyDeviceToDevice, 0);
    cudaMemsetAsync(la, 0, (size_t)B_DIM * NB * NB * sizeof(float), 0);
    kpmb_kernel<<<8, 256>>>(kpm, kpmb);
    bucket_mean_h_kernel<<<(B_DIM * NB * E_DIM) / 256, 256>>>(query, qkmh);
    bucket_mean_h_kernel<<<(B_DIM * NB * E_DIM) / 256, 256>>>(key_t, qkmh + QK_STRIDE);

    // main: batched Q+K projection (needs weight cvt from s2)
    cudaStreamWaitEvent(0, evW, 0);
    hgemm_kernel<false, true, true, false><<<dim3(8, 16, 2), 256, HG_SMEM_N>>>(
        qkbh, qkmh, Wqkh, bqk, 2048, 1024, 1024, 1024, 1.0f,
        (long)QK_STRIDE, (long)EE, (long)QK_STRIDE);

    // main: attn logits split-K x2 into zeroed la
    hgemm_kernel<false, false, false, true><<<dim3(2, 2, 2 * B_DIM), 256, HG_SMEM_N>>>(
        la, qkbh, qkbh + QK_STRIDE, nullptr, 256, 256, 512, 1024, ATTN_ALPHA,
        (long)NB * E_DIM, (long)NB * E_DIM, (long)NB * NB);

    // main: sinkhorn (mask fused) -> ph, rowsum
    sinkhorn_kernel<<<B_DIM, 1024>>>(la, kpmb, ph, rowsum);

    // main: zmix (needs vh from s1)
    cudaStreamWaitEvent(0, evV, 0);
    zmix_hmma_kernel<<<dim3(8, 32, 8), 256, ZSMEM>>>(ph, vh, zh);

    // main: final GEMM (needs wvoh/bvo from s2)
    cudaStreamWaitEvent(0, evSide, 0);
    hmma_out_kernel<<<dim3(4, 256, 1), 256, HMMA_SMEM>>>(
        out, zh, wvoh, bo, bvo, rowsum);
}

// round 15
// speedup vs baseline: 1.1472x; 1.1103x over previous
#include <cuda_runtime.h>
#include <cuda_bf16.h>
#include <cuda_fp16.h>
#include <math.h>
#include <cstdint>

// ---------------- problem constants ----------------
#define T_DIM 4096
#define S_DIM 4096
#define B_DIM 8
#define E_DIM 1024
#define BUCKET 16
#define NB 256            // T/BUCKET
#define TAU 0.75f
#define ATTN_ALPHA (1.0f/(32.0f*0.75f))
#define QK_STRIDE (B_DIM*NB*E_DIM)   // 2097152

// ---------------- scratch (device globals; no allocation allowed) ----------------
__device__ __half g_qkmh[2*QK_STRIDE];      // bucket means q|k, fp16
__device__ __half g_qkbh[2*QK_STRIDE];      // projected bucket q|k, fp16
__device__ __half g_Wqkh[2*E_DIM*E_DIM];    // Wq|Wk fp16
__device__ __half g_Wvh[E_DIM*E_DIM];
__device__ __half g_Woh[E_DIM*E_DIM];
__device__ float g_bqk[2*E_DIM];            // bq|bk fp32
__device__ float g_la[B_DIM*NB*NB];
__device__ __half g_ph[B_DIM*NB*NB];        // sinkhorn result, fp16
__device__ float g_rowsum[B_DIM*NB];
__device__ int   g_kpmb[B_DIM*NB];
__device__ float g_bvo[E_DIM];              // Wo @ bv
__device__ __half g_vh[S_DIM*B_DIM*E_DIM];  // value in fp16
__device__ __half g_zh[T_DIM*B_DIM*E_DIM];  // mixed value, fp16 (rows m=t*8+b)
__device__ __half g_wvoh[E_DIM*E_DIM];      // Wo @ Wv in fp16
__device__ float g_colpart[8*B_DIM*4*NB];   // sinkhorn partial colsums [it][b][part][256]
__device__ int   g_bar[8*B_DIM];            // sinkhorn barriers [it][b]

// =================== warp-MMA helpers (compute_80-compatible PTX) ===================
__device__ __forceinline__ uint32_t smem_u32(const void* p) {
    uint32_t a;
    asm("{ .reg .u64 t; cvta.to.shared.u64 t, %1; cvt.u32.u64 %0, t; }" : "=r"(a) : "l"(p));
    return a;
}

#define CP_ASYNC16(dst, src) \
    asm volatile("cp.async.cg.shared.global [%0], [%1], 16;" :: "r"(dst), "l"(src))
#define CP_COMMIT() asm volatile("cp.async.commit_group;")
#define CP_WAIT3()  asm volatile("cp.async.wait_group 3;")
#define CP_WAIT1()  asm volatile("cp.async.wait_group 1;")
#define CP_WAIT0()  asm volatile("cp.async.wait_group 0;")

#define LDSM_X4(r0, r1, r2, r3, addr) \
    asm volatile("ldmatrix.sync.aligned.m8n8.x4.shared.b16 {%0,%1,%2,%3}, [%4];" \
        : "=r"(r0), "=r"(r1), "=r"(r2), "=r"(r3) : "r"(addr))

#define LDSM_X4_T(r0, r1, r2, r3, addr) \
    asm volatile("ldmatrix.sync.aligned.m8n8.x4.trans.shared.b16 {%0,%1,%2,%3}, [%4];" \
        : "=r"(r0), "=r"(r1), "=r"(r2), "=r"(r3) : "r"(addr))

#define MMA16816F16(d, a0, a1, a2, a3, b0, b1) \
    asm volatile("mma.sync.aligned.m16n8k16.row.col.f32.f16.f16.f32 " \
        "{%0,%1,%2,%3}, {%4,%5,%6,%7}, {%8,%9}, {%0,%1,%2,%3};" \
        : "+f"((d)[0]), "+f"((d)[1]), "+f"((d)[2]), "+f"((d)[3]) \
        : "r"(a0), "r"(a1), "r"(a2), "r"(a3), "r"(b0), "r"(b1))

// =================== generic fp16 HMMA GEMM (frozen core) ===================
#define HG_A_ROW 80
#define HG_A_TILE (128*HG_A_ROW)   // 10240
#define HG_BT_ROW 272
#define HG_BT_TILE (32*HG_BT_ROW)  // 8704

template <bool BTRANS, bool BIAS, bool OUT_HALF, bool SPLITK>
__global__ __launch_bounds__(256)
void hgemm_kernel(void* __restrict__ Cv, const __half* __restrict__ A,
                  const __half* __restrict__ B, const float* __restrict__ bias,
                  int M, int N, int K, int lda, float alpha, long sA, long sB, long sC) {
    constexpr int B_TILE = BTRANS ? HG_BT_TILE : HG_A_TILE;
    constexpr int STAGE = HG_A_TILE + B_TILE;
    extern __shared__ char smem[];
    uint32_t sbase = smem_u32(smem);

    int z = blockIdx.z;
    long cofs;
    if (SPLITK) {
        int zb = z >> 1, zs = z & 1;
        A += (long)zb * sA + zs * K;
        B += (long)zb * sB + zs * K;
        cofs = (long)zb * sC;
    } else {
        A += (long)z * sA; B += (long)z * sB;
        cofs = (long)z * sC;
    }

    int tid = threadIdx.x, wid = tid >> 5, lane = tid & 31;
    int bm = blockIdx.y * 128, bn = blockIdx.x * 128;
    int wm = (wid & 1) * 64, wn = (wid >> 1) * 32;

    float acc[4][4][4];
#pragma unroll
    for (int i = 0; i < 4; i++)
#pragma unroll
        for (int j = 0; j < 4; j++)
#pragma unroll
            for (int r = 0; r < 4; r++) acc[i][j][r] = 0.f;

    auto stage_load = [&](int kt, int buf) {
        int k0 = kt * 32;
        uint32_t base = sbase + buf * STAGE;
#pragma unroll
        for (int q = 0; q < 2; q++) {
            int c = tid + q * 256;
            int row = c >> 2, seg = c & 3;
            CP_ASYNC16(base + row * HG_A_ROW + seg * 16,
                       A + (size_t)(bm + row) * lda + k0 + seg * 8);
        }
        if (!BTRANS) {
#pragma unroll
            for (int q = 0; q < 2; q++) {
                int c = tid + q * 256;
                int row = c >> 2, seg = c & 3;
                CP_ASYNC16(base + HG_A_TILE + row * HG_A_ROW + seg * 16,
                           B + (size_t)(bn + row) * lda + k0 + seg * 8);
            }
        } else {
#pragma unroll
            for (int q = 0; q < 2; q++) {
                int c = tid + q * 256;
                int kk = c >> 4, seg = c & 15;
                CP_ASYNC16(base + HG_A_TILE + kk * HG_BT_ROW + seg * 16,
                           B + (size_t)(k0 + kk) * N + bn + seg * 8);
            }
        }
        CP_COMMIT();
    };

    int lrow = lane & 15, lhi = lane >> 4;

    stage_load(0, 0);
    int NKT = K / 32;
    for (int kt = 0; kt < NKT; kt++) {
        if (kt + 1 < NKT) { stage_load(kt + 1, (kt + 1) & 1); CP_WAIT1(); }
        else CP_WAIT0();
        __syncthreads();

        uint32_t base = sbase + (kt & 1) * STAGE;
        uint32_t aS = base, bS = base + HG_A_TILE;

#pragma unroll
        for (int ks = 0; ks < 2; ks++) {
            uint32_t a[4][4], bt[2][4];
#pragma unroll
            for (int mt = 0; mt < 4; mt++) {
                uint32_t off = (wm + mt * 16 + lrow) * HG_A_ROW + (ks * 16 + lhi * 8) * 2;
                LDSM_X4(a[mt][0], a[mt][1], a[mt][2], a[mt][3], aS + off);
            }
            if (!BTRANS) {
#pragma unroll
                for (int nt = 0; nt < 2; nt++) {
                    uint32_t off = (wn + nt * 16 + lrow) * HG_A_ROW + (ks * 16 + lhi * 8) * 2;
                    LDSM_X4(bt[nt][0], bt[nt][1], bt[nt][2], bt[nt][3], bS + off);
                }
#pragma unroll
                for (int mt = 0; mt < 4; mt++)
#pragma unroll
                    for (int j = 0; j < 4; j++) {
                        int nt = j >> 1, hi = j & 1;
                        MMA16816F16(acc[mt][j], a[mt][0], a[mt][1], a[mt][2], a[mt][3],
                                    bt[nt][hi], bt[nt][hi + 2]);
                    }
            } else {
#pragma unroll
                for (int ng = 0; ng < 2; ng++) {
                    uint32_t off = (ks * 16 + lrow) * HG_BT_ROW + (wn + ng * 16 + lhi * 8) * 2;
                    LDSM_X4_T(bt[ng][0], bt[ng][1], bt[ng][2], bt[ng][3], bS + off);
                }
#pragma unroll
                for (int mt = 0; mt < 4; mt++)
#pragma unroll
                    for (int j = 0; j < 4; j++) {
                        int ng = j >> 1, hi = j & 1;
                        MMA16816F16(acc[mt][j], a[mt][0], a[mt][1], a[mt][2], a[mt][3],
                                    bt[ng][hi * 2], bt[ng][hi * 2 + 1]);
                    }
            }
        }
        __syncthreads();
    }

    // ---- epilogue ----
#pragma unroll
    for (int mt = 0; mt < 4; mt++) {
        int m0 = bm + wm + mt * 16 + (lane >> 2);
        int m1 = m0 + 8;
#pragma unroll
        for (int j = 0; j < 4; j++) {
            int n = bn + wn + j * 8 + (lane & 3) * 2;
            float v00 = acc[mt][j][0] * alpha, v01 = acc[mt][j][1] * alpha;
            float v10 = acc[mt][j][2] * alpha, v11 = acc[mt][j][3] * alpha;
            if (BIAS) {
                float b0 = bias[(long)blockIdx.z * N + n], b1 = bias[(long)blockIdx.z * N + n + 1];
                v00 += b0; v01 += b1; v10 += b0; v11 += b1;
            }
            if (SPLITK) {
                float* C = (float*)Cv + cofs;
                atomicAdd(C + (size_t)m0 * N + n, v00);
                atomicAdd(C + (size_t)m0 * N + n + 1, v01);
                atomicAdd(C + (size_t)m1 * N + n, v10);
                atomicAdd(C + (size_t)m1 * N + n + 1, v11);
            } else if (OUT_HALF) {
                __half* C = (__half*)Cv + cofs;
                *(__half2*)(C + (size_t)m0 * N + n) = __floats2half2_rn(v00, v01);
                *(__half2*)(C + (size_t)m1 * N + n) = __floats2half2_rn(v10, v11);
            } else {
                float* C = (float*)Cv + cofs;
                *(float2*)(C + (size_t)m0 * N + n) = make_float2(v00, v01);
                *(float2*)(C + (size_t)m1 * N + n) = make_float2(v10, v11);
            }
        }
    }
}

// =================== final GEMM (frozen champion config; ybase added) ===================
#define KC 32
#define ROW_B 80
#define A_TILE_B (128*ROW_B)
#define B_TILE_B (256*ROW_B)
#define STAGE_B (A_TILE_B + B_TILE_B)
#define HMMA_SMEM (4*STAGE_B)

__global__ __launch_bounds__(256, 1)
void hmma_out_kernel(float* __restrict__ out,
                     const __half* __restrict__ Ah, const __half* __restrict__ Bh,
                     const float* __restrict__ bo, const float* __restrict__ bvo,
                     const float* __restrict__ rowsum, int ybase) {
    extern __shared__ char smem[];
    uint32_t sbase = smem_u32(smem);

    int tid = threadIdx.x, wid = tid >> 5, lane = tid & 31;
    int bm = (blockIdx.y + ybase) * 128, bn = blockIdx.x * 256;
    int wm = (wid & 1) * 64, wn = (wid >> 1) * 64;

    const __half* Ag = Ah + (size_t)bm * 1024;
    const __half* Bg = Bh + (size_t)bn * 1024;

    float acc[4][8][4];
#pragma unroll
    for (int i = 0; i < 4; i++)
#pragma unroll
        for (int j = 0; j < 8; j++)
#pragma unroll
            for (int r = 0; r < 4; r++) acc[i][j][r] = 0.f;

    auto stage_load = [&](int kt, int buf) {
        int k0 = kt * KC;
        uint32_t base = sbase + buf * STAGE_B;
#pragma unroll
        for (int q = 0; q < 2; q++) {
            int c = tid + q * 256;
            int row = c >> 2, seg = c & 3;
            CP_ASYNC16(base + row * ROW_B + seg * 16,
                       Ag + (size_t)row * 1024 + k0 + seg * 8);
        }
#pragma unroll
        for (int q = 0; q < 4; q++) {
            int c = tid + q * 256;
            int row = c >> 2, seg = c & 3;
            CP_ASYNC16(base + A_TILE_B + row * ROW_B + seg * 16,
                       Bg + (size_t)row * 1024 + k0 + seg * 8);
        }
    };

    int lrow = lane & 15, lkseg = (lane >> 4) * 8;

    stage_load(0, 0); CP_COMMIT();
    stage_load(1, 1); CP_COMMIT();
    stage_load(2, 2); CP_COMMIT();

    const int NKT = 1024 / KC;
    for (int kt = 0; kt < NKT; kt++) {
        if (kt + 3 < NKT) stage_load(kt + 3, (kt + 3) & 3);
        CP_COMMIT();
        CP_WAIT3();
        __syncthreads();

        uint32_t base = sbase + (kt & 3) * STAGE_B;
        uint32_t aS = base, bS = base + A_TILE_B;

#pragma unroll
        for (int ks = 0; ks < KC / 16; ks++) {
            int kb = (ks * 16 + lkseg) * 2;
            uint32_t a[4][4], b[4][4];
#pragma unroll
            for (int mt = 0; mt < 4; mt++) {
                uint32_t off = (wm + mt * 16 + lrow) * ROW_B + kb;
                LDSM_X4(a[mt][0], a[mt][1], a[mt][2], a[mt][3], aS + off);
            }
#pragma unroll
            for (int nt = 0; nt < 4; nt++) {
                uint32_t off = (wn + nt * 16 + lrow) * ROW_B + kb;
                LDSM_X4(b[nt][0], b[nt][1], b[nt][2], b[nt][3], bS + off);
            }
#pragma unroll
            for (int mt = 0; mt < 4; mt++) {
#pragma unroll
                for (int j = 0; j < 8; j++) {
                    int nt = j >> 1, hi = j & 1;
                    MMA16816F16(acc[mt][j], a[mt][0], a[mt][1], a[mt][2], a[mt][3],
                                b[nt][hi], b[nt][hi + 2]);
                }
            }
        }
        __syncthreads();
    }

#pragma unroll
    for (int mt = 0; mt < 4; mt++) {
        int m0 = bm + wm + mt * 16 + (lane >> 2);
        int m1 = m0 + 8;
        float rs0 = rowsum[((m0 & 7) << 8) | (m0 >> 7)];
        float rs1 = rowsum[((m1 & 7) << 8) | (m1 >> 7)];
#pragma unroll
        for (int j = 0; j < 8; j++) {
            int n = bn + wn + j * 8 + (lane & 3) * 2;
            float b0 = bo[n], b1 = bo[n + 1], v0 = bvo[n], v1 = bvo[n + 1];
            *(float2*)(out + (size_t)m0 * 1024 + n) =
                make_float2(acc[mt][j][0] + b0 + rs0 * v0, acc[mt][j][1] + b1 + rs0 * v1);
            *(float2*)(out + (size_t)m1 * 1024 + n) =
                make_float2(acc[mt][j][2] + b0 + rs1 * v0, acc[mt][j][3] + b1 + rs1 * v1);
        }
    }
}

// =================== zmix as fp16 warp-MMA (frozen champion; mt0 param) ===================
#define ZA_ROW_B 80
#define ZA_TILE_B (128*ZA_ROW_B)
#define ZB_ROW_B 272
#define ZB_TILE_B (32*ZB_ROW_B)
#define ZSTAGE_B (ZA_TILE_B + ZB_TILE_B)
#define ZSMEM (2*ZSTAGE_B)

__global__ __launch_bounds__(256, 1)
void zmix_hmma_kernel(const __half* __restrict__ Ph, const __half* __restrict__ Vh,
                      __half* __restrict__ Zh, int mt0) {
    extern __shared__ char smem[];
    uint32_t sbase = smem_u32(smem);

    int tid = threadIdx.x, wid = tid >> 5, lane = tid & 31;
    int b = blockIdx.z;
    int pos = blockIdx.y;
    int bm = mt0 * 128, bn = blockIdx.x * 128;
    int wm = (wid & 1) * 64, wn = (wid >> 1) * 32;

    const __half* Ag = Ph + (size_t)b * (NB * NB) + (size_t)bm * 256;

    float acc[4][4][4];
#pragma unroll
    for (int i = 0; i < 4; i++)
#pragma unroll
        for (int j = 0; j < 4; j++)
#pragma unroll
            for (int r = 0; r < 4; r++) acc[i][j][r] = 0.f;

    auto stage_load = [&](int kt, int buf) {
        int k0 = kt * 32;
        uint32_t base = sbase + buf * ZSTAGE_B;
#pragma unroll
        for (int q = 0; q < 2; q++) {
            int c = tid + q * 256;
            int row = c >> 2, seg = c & 3;
            CP_ASYNC16(base + row * ZA_ROW_B + seg * 16,
                       Ag + (size_t)row * 256 + k0 + seg * 8);
        }
#pragma unroll
        for (int q = 0; q < 2; q++) {
            int c = tid + q * 256;
            int kk = c >> 4, seg = c & 15;
            size_t grow = (size_t)(16 * (k0 + kk) + pos) * (B_DIM * E_DIM) + b * E_DIM + bn;
            CP_ASYNC16(base + ZA_TILE_B + kk * ZB_ROW_B + seg * 16, Vh + grow + seg * 8);
        }
        CP_COMMIT();
    };

    int lrow = lane & 15, lhi = lane >> 4;

    stage_load(0, 0);
    for (int kt = 0; kt < 8; kt++) {
        if (kt + 1 < 8) { stage_load(kt + 1, (kt + 1) & 1); CP_WAIT1(); }
        else CP_WAIT0();
        __syncthreads();

        uint32_t base = sbase + (kt & 1) * ZSTAGE_B;
        uint32_t aS = base, bS = base + ZA_TILE_B;

#pragma unroll
        for (int ks = 0; ks < 2; ks++) {
            uint32_t a[4][4], bt[2][4];
#pragma unroll
            for (int mt = 0; mt < 4; mt++) {
                uint32_t off = (wm + mt * 16 + lrow) * ZA_ROW_B + (ks * 16 + lhi * 8) * 2;
                LDSM_X4(a[mt][0], a[mt][1], a[mt][2], a[mt][3], aS + off);
            }
#pragma unroll
            for (int ng = 0; ng < 2; ng++) {
                uint32_t off = (ks * 16 + lrow) * ZB_ROW_B + (wn + ng * 16 + lhi * 8) * 2;
                LDSM_X4_T(bt[ng][0], bt[ng][1], bt[ng][2], bt[ng][3], bS + off);
            }
#pragma unroll
            for (int mt = 0; mt < 4; mt++) {
#pragma unroll
                for (int j = 0; j < 4; j++) {
                    int ng = j >> 1, hi = j & 1;
                    MMA16816F16(acc[mt][j], a[mt][0], a[mt][1], a[mt][2], a[mt][3],
                                bt[ng][hi * 2], bt[ng][hi * 2 + 1]);
                }
            }
        }
        __syncthreads();
    }

#pragma unroll
    for (int mt = 0; mt < 4; mt++) {
        int tb0 = bm + wm + mt * 16 + (lane >> 2);
        int tb1 = tb0 + 8;
        size_t r0 = ((size_t)(tb0 * 16 + pos) * 8 + b) * 1024;
        size_t r1 = ((size_t)(tb1 * 16 + pos) * 8 + b) * 1024;
#pragma unroll
        for (int j = 0; j < 4; j++) {
            int e = bn + wn + j * 8 + (lane & 3) * 2;
            *(__half2*)(Zh + r0 + e) = __floats2half2_rn(acc[mt][j][0], acc[mt][j][1]);
            *(__half2*)(Zh + r1 + e) = __floats2half2_rn(acc[mt][j][2], acc[mt][j][3]);
        }
    }
}

// =================== elementwise / small kernels ===================
__global__ void bucket_mean_h_kernel(const float* __restrict__ X, __half* __restrict__ out) {
    int o = blockIdx.x * 256 + threadIdx.x;
    int e = o & (E_DIM - 1);
    int m = o >> 10;
    int b = m >> 8;
    int i = m & 255;
    const float* src = X + (size_t)(i * BUCKET) * (B_DIM * E_DIM) + b * E_DIM + e;
    float s = 0.f;
#pragma unroll
    for (int pos = 0; pos < BUCKET; pos++) s += src[(size_t)pos * (B_DIM * E_DIM)];
    out[o] = __float2half_rn(s * (1.0f / BUCKET));
}

__global__ void kpmb_kernel(const unsigned char* __restrict__ mask, int* __restrict__ kpmb) {
    int j = blockIdx.x * 256 + threadIdx.x;
    if (j >= B_DIM * NB) return;
    int b = j >> 8, s = j & 255;
    const unsigned char* m = mask + b * S_DIM + s * BUCKET;
    int all = 1;
#pragma unroll
    for (int t = 0; t < BUCKET; t++) all &= (m[t] != 0);
    kpmb[j] = all;
}

__global__ void bvo_kernel(const float* __restrict__ Wo, const float* __restrict__ bv,
                           float* __restrict__ bvo) {
    int g = blockIdx.x * 8 + (threadIdx.x >> 5);
    int l = threadIdx.x & 31;
    if (g >= E_DIM) return;
    float s = 0.f;
    for (int k = l; k < E_DIM; k += 32) s += Wo[(size_t)g * E_DIM + k] * bv[k];
#pragma unroll
    for (int off = 16; off; off >>= 1) s += __shfl_xor_sync(0xffffffffu, s, off);
    if (l == 0) bvo[g] = s;
}

__global__ void cvt8_kernel(const float* __restrict__ X, __half* __restrict__ H) {
    size_t i = ((size_t)blockIdx.x * 256 + threadIdx.x) * 8;
    float4 a = *(const float4*)(X + i);
    float4 c = *(const float4*)(X + i + 4);
    __half2 h[4];
    h[0] = __floats2half2_rn(a.x, a.y);
    h[1] = __floats2half2_rn(a.z, a.w);
    h[2] = __floats2half2_rn(c.x, c.y);
    h[3] = __floats2half2_rn(c.z, c.w);
    *(uint4*)(H + i) = *(uint4*)h;
}

__global__ void cvt8x4_kernel(const float* __restrict__ W0, const float* __restrict__ W1,
                              const float* __restrict__ W2, const float* __restrict__ W3,
                              __half* __restrict__ H0, __half* __restrict__ H1,
                              __half* __restrict__ H2, __half* __restrict__ H3) {
    const float* X = (blockIdx.y == 0) ? W0 : (blockIdx.y == 1) ? W1 : (blockIdx.y == 2) ? W2 : W3;
    __half* H = (blockIdx.y == 0) ? H0 : (blockIdx.y == 1) ? H1 : (blockIdx.y == 2) ? H2 : H3;
    size_t i = ((size_t)blockIdx.x * 256 + threadIdx.x) * 8;
    float4 a = *(const float4*)(X + i);
    float4 c = *(const float4*)(X + i + 4);
    __half2 h[4];
    h[0] = __floats2half2_rn(a.x, a.y);
    h[1] = __floats2half2_rn(a.z, a.w);
    h[2] = __floats2half2_rn(c.x, c.y);
    h[3] = __floats2half2_rn(c.z, c.w);
    *(uint4*)(H + i) = *(uint4*)h;
}

// ---------------- sinkhorn: 4 CTAs per batch, deterministic cross-CTA colsum ----------------
// grid 32 CTAs, 1024 threads. CTA (b, part) owns rows part*64..part*64+63.
// Partial colsums go to private slots; spin barrier on int counters (memset per launch).
__global__ __launch_bounds__(1024, 1)
void sinkhorn_kernel(float* __restrict__ la, const int* __restrict__ kpmb,
                     __half* __restrict__ ph, float* __restrict__ rowsum,
                     float* __restrict__ colpart, int* __restrict__ bar) {
    int b = blockIdx.x >> 2, part = blockIdx.x & 3;
    float* base = la + b * (NB * NB);
    int tid = threadIdx.x, w = tid >> 5, l = tid & 31;
    __shared__ float sh[32 * 256];
    __shared__ float colv[256];
    __shared__ int mflag[256];
    if (tid < 256) { colv[tid] = 0.f; mflag[tid] = kpmb[b * 256 + tid]; }
    __syncthreads();

    int cf[8];
#pragma unroll
    for (int ci = 0; ci < 8; ci++) cf[ci] = mflag[ci * 32 + l];

    for (int it = 0; it < 8; it++) {
        float cv[8], cs[8];
#pragma unroll
        for (int ci = 0; ci < 8; ci++) { cv[ci] = colv[ci * 32 + l]; cs[ci] = 0.f; }
#pragma unroll
        for (int ri = 0; ri < 2; ri++) {
            int r = part * 64 + w * 2 + ri;
            float v[8];
#pragma unroll
            for (int ci = 0; ci < 8; ci++) v[ci] = base[r * 256 + ci * 32 + l] - cv[ci];
            float m = 0.f;
            if (it == 0) {
                int rf = mflag[r];
#pragma unroll
                for (int ci = 0; ci < 8; ci++) if (rf != cf[ci]) v[ci] = -1e30f;
                m = v[0];
#pragma unroll
                for (int ci = 1; ci < 8; ci++) m = fmaxf(m, v[ci]);
#pragma unroll
                for (int off = 16; off; off >>= 1) m = fmaxf(m, __shfl_xor_sync(0xffffffffu, m, off));
            }
            float e[8];
            float s = 0.f;
#pragma unroll
            for (int ci = 0; ci < 8; ci++) { e[ci] = __expf(v[ci] - m); s += e[ci]; }
#pragma unroll
            for (int off = 16; off; off >>= 1) s += __shfl_xor_sync(0xffffffffu, s, off);
            float lse = m + __logf(s);
            float inv = __fdividef(1.0f, s);
#pragma unroll
            for (int ci = 0; ci < 8; ci++) {
                base[r * 256 + ci * 32 + l] = v[ci] - lse;
                cs[ci] += e[ci] * inv;
            }
        }
#pragma unroll
        for (int ci = 0; ci < 8; ci++) sh[w * 256 + ci * 32 + l] = cs[ci];
        __syncthreads();
        if (tid < 256) {
            float s = 0.f;
#pragma unroll 4
            for (int ww = 0; ww < 32; ww++) s += sh[ww * 256 + tid];
            colpart[(((it * B_DIM + b) * 4 + part) << 8) + tid] = s;
        }
        __threadfence();
        __syncthreads();
        if (tid == 0) {
            int* pb = bar + it * B_DIM + b;
            atomicAdd(pb, 1);
            while (atomicAdd(pb, 0) < 4) { }
        }
        __syncthreads();
        if (tid < 256) {
            const float* cp = colpart + (((it * B_DIM + b) * 4) << 8) + tid;
            float s = __ldcg(cp) + __ldcg(cp + 256) + __ldcg(cp + 512) + __ldcg(cp + 768);
            colv[tid] = __logf(s);
        }
        __syncthreads();
    }

    // epilogue: p = exp(la - colv) -> fp16, rowsum fp32  (rows owned by this CTA)
    float cv[8];
#pragma unroll
    for (int ci = 0; ci < 8; ci++) cv[ci] = colv[ci * 32 + l];
#pragma unroll
    for (int ri = 0; ri < 2; ri++) {
        int r = part * 64 + w * 2 + ri;
        float s = 0.f;
#pragma unroll
        for (int ci = 0; ci < 8; ci++) {
            float e = __expf(base[r * 256 + ci * 32 + l] - cv[ci]);
            ph[b * (NB * NB) + r * 256 + ci * 32 + l] = __float2half_rn(e);
            s += e;
        }
#pragma unroll
        for (int off = 16; off; off >>= 1) s += __shfl_xor_sync(0xffffffffu, s, off);
        if (l == 0) rowsum[b * 256 + r] = s;
    }
}

// ---------------- launch (multi-stream fork/join + zmix/hmma pipelining) ----------------
extern "C" void kernel_launch(void* const* d_in, const int* in_sizes, int n_in,
                              void* d_out, int out_size) {
    const float* query = (const float*)d_in[0];
    const float* key_t = (const float*)d_in[1];
    const float* value = (const float*)d_in[2];
    const unsigned char* kpm = (const unsigned char*)d_in[3];
    const float* Wq = (const float*)d_in[4];
    const float* bq = (const float*)d_in[5];
    const float* Wk = (const float*)d_in[6];
    const float* bk = (const float*)d_in[7];
    const float* Wv = (const float*)d_in[8];
    const float* bv = (const float*)d_in[9];
    const float* Wo = (const float*)d_in[10];
    const float* bo = (const float*)d_in[11];
    float* out = (float*)d_out;

    float *la, *rowsum, *bvo, *bqk, *colpart;
    __half *qkmh, *qkbh, *Wqkh, *Wvh, *Woh, *ph, *vh, *zh, *wvoh;
    int *kpmb, *bar;
    cudaGetSymbolAddress((void**)&qkmh, g_qkmh);
    cudaGetSymbolAddress((void**)&qkbh, g_qkbh);
    cudaGetSymbolAddress((void**)&Wqkh, g_Wqkh);
    cudaGetSymbolAddress((void**)&Wvh, g_Wvh);
    cudaGetSymbolAddress((void**)&Woh, g_Woh);
    cudaGetSymbolAddress((void**)&bqk, g_bqk);
    cudaGetSymbolAddress((void**)&la, g_la);
    cudaGetSymbolAddress((void**)&ph, g_ph);
    cudaGetSymbolAddress((void**)&rowsum, g_rowsum);
    cudaGetSymbolAddress((void**)&kpmb, g_kpmb);
    cudaGetSymbolAddress((void**)&bvo, g_bvo);
    cudaGetSymbolAddress((void**)&vh, g_vh);
    cudaGetSymbolAddress((void**)&zh, g_zh);
    cudaGetSymbolAddress((void**)&wvoh, g_wvoh);
    cudaGetSymbolAddress((void**)&colpart, g_colpart);
    cudaGetSymbolAddress((void**)&bar, g_bar);

    static cudaStream_t s1 = nullptr, s2 = nullptr;
    static cudaEvent_t evRoot, evW, evV, evSide, evSink, evZB;
    static bool init_done = false;
    if (!init_done) {
        cudaFuncSetAttribute(hmma_out_kernel, cudaFuncAttributeMaxDynamicSharedMemorySize, HMMA_SMEM);
        cudaStreamCreateWithFlags(&s1, cudaStreamNonBlocking);
        cudaStreamCreateWithFlags(&s2, cudaStreamNonBlocking);
        cudaEventCreateWithFlags(&evRoot, cudaEventDisableTiming);
        cudaEventCreateWithFlags(&evW, cudaEventDisableTiming);
        cudaEventCreateWithFlags(&evV, cudaEventDisableTiming);
        cudaEventCreateWithFlags(&evSide, cudaEventDisableTiming);
        cudaEventCreateWithFlags(&evSink, cudaEventDisableTiming);
        cudaEventCreateWithFlags(&evZB, cudaEventDisableTiming);
        init_done = true;
    }

    const int HG_SMEM_N = 2 * (HG_A_TILE + HG_A_TILE);   // 40960
    const int HG_SMEM_T = 2 * (HG_A_TILE + HG_BT_TILE);  // 37888
    const int EE = E_DIM * E_DIM;

    // ---- fork side streams ----
    cudaEventRecord(evRoot, 0);
    cudaStreamWaitEvent(s1, evRoot, 0);
    cudaStreamWaitEvent(s2, evRoot, 0);

    // s1: value -> fp16
    cvt8_kernel<<<(S_DIM * B_DIM * E_DIM) / 2048, 256, 0, s1>>>(value, vh);
    cudaEventRecord(evV, s1);

    // s2: weight converts -> wvo + bvo
    cvt8x4_kernel<<<dim3(EE / 2048, 4), 256, 0, s2>>>(Wq, Wk, Wv, Wo,
                                                      Wqkh, Wqkh + EE, Wvh, Woh);
    cudaEventRecord(evW, s2);
    hgemm_kernel<true, false, true, false><<<dim3(8, 8, 1), 256, HG_SMEM_T, s2>>>(
        wvoh, Woh, Wvh, nullptr, 1024, 1024, 1024, 1024, 1.0f, 0, 0, 0);
    bvo_kernel<<<128, 256, 0, s2>>>(Wo, bv, bvo);
    cudaEventRecord(evSide, s2);

    // main: bias pack, zero la + barriers, mask flags, bucket means
    cudaMemcpyAsync(bqk, bq, E_DIM * sizeof(float), cudaMemcpyDeviceToDevice, 0);
    cudaMemcpyAsync(bqk + E_DIM, bk, E_DIM * sizeof(float), cudaMemcpyDeviceToDevice, 0);
    cudaMemsetAsync(la, 0, (size_t)B_DIM * NB * NB * sizeof(float), 0);
    cudaMemsetAsync(bar, 0, 8 * B_DIM * sizeof(int), 0);
    kpmb_kernel<<<8, 256>>>(kpm, kpmb);
    bucket_mean_h_kernel<<<(B_DIM * NB * E_DIM) / 256, 256>>>(query, qkmh);
    bucket_mean_h_kernel<<<(B_DIM * NB * E_DIM) / 256, 256>>>(key_t, qkmh + QK_STRIDE);

    // main: batched Q+K projection
    cudaStreamWaitEvent(0, evW, 0);
    hgemm_kernel<false, true, true, false><<<dim3(8, 16, 2), 256, HG_SMEM_N>>>(
        qkbh, qkmh, Wqkh, bqk, 2048, 1024, 1024, 1024, 1.0f,
        (long)QK_STRIDE, (long)EE, (long)QK_STRIDE);

    // main: attn logits split-K x2
    hgemm_kernel<false, false, false, true><<<dim3(2, 2, 2 * B_DIM), 256, HG_SMEM_N>>>(
        la, qkbh, qkbh + QK_STRIDE, nullptr, 256, 256, 512, 1024, ATTN_ALPHA,
        (long)NB * E_DIM, (long)NB * E_DIM, (long)NB * NB);

    // main: sinkhorn (32 CTAs, 4 per batch)
    sinkhorn_kernel<<<32, 1024>>>(la, kpmb, ph, rowsum, colpart, bar);
    cudaEventRecord(evSink, 0);

    // s1: zmix half B (tb 128..255) — runs concurrently with hmma_A below
    cudaStreamWaitEvent(s1, evSink, 0);
    zmix_hmma_kernel<<<dim3(8, 16, 8), 256, ZSMEM, s1>>>(ph, vh, zh, 1);
    cudaEventRecord(evZB, s1);

    // main: zmix half A (tb 0..127)
    cudaStreamWaitEvent(0, evV, 0);
    zmix_hmma_kernel<<<dim3(8, 16, 8), 256, ZSMEM>>>(ph, vh, zh, 0);

    // main: hmma half A (m rows 0..16383, uses Z of tb 0..127)
    cudaStreamWaitEvent(0, evSide, 0);
    hmma_out_kernel<<<dim3(4, 128, 1), 256, HMMA_SMEM>>>(
        out, zh, wvoh, bo, bvo, rowsum, 0);

    // main: hmma half B (needs zmix half B)
    cudaStreamWaitEvent(0, evZB, 0);
    hmma_out_kernel<<<dim3(4, 128, 1), 256, HMMA_SMEM>>>(
        out, zh, wvoh, bo, bvo, rowsum, 128);
}

// round 16
// speedup vs baseline: 1.2353x; 1.0768x over previous
#include <cuda_runtime.h>
#include <cuda_bf16.h>
#include <cuda_fp16.h>
#include <math.h>
#include <cstdint>

// ---------------- problem constants ----------------
#define T_DIM 4096
#define S_DIM 4096
#define B_DIM 8
#define E_DIM 1024
#define BUCKET 16
#define NB 256            // T/BUCKET
#define TAU 0.75f
#define ATTN_ALPHA (1.0f/(32.0f*0.75f))
#define QK_STRIDE (B_DIM*NB*E_DIM)   // 2097152

// ---------------- scratch (device globals; no allocation allowed) ----------------
__device__ __half g_qkmh[2*QK_STRIDE];      // bucket means q|k, fp16
__device__ __half g_qkbh[2*QK_STRIDE];      // projected bucket q|k, fp16
__device__ __half g_Wqkh[2*E_DIM*E_DIM];    // Wq|Wk fp16
__device__ __half g_Wvh[E_DIM*E_DIM];
__device__ __half g_Woh[E_DIM*E_DIM];
__device__ float g_bqk[2*E_DIM];            // bq|bk fp32
__device__ float g_la[B_DIM*NB*NB];
__device__ __half g_ph[B_DIM*NB*NB];        // sinkhorn result, fp16
__device__ float g_rowsum[B_DIM*NB];
__device__ int   g_kpmb[B_DIM*NB];
__device__ float g_bvo[E_DIM];              // Wo @ bv
__device__ __half g_vh[S_DIM*B_DIM*E_DIM];  // value in fp16
__device__ __half g_yh[S_DIM*B_DIM*E_DIM];  // Y = V @ wvo^T, fp16 (rows m=s*8+b)
__device__ __half g_wvoh[E_DIM*E_DIM];      // Wo @ Wv in fp16
__device__ float g_colpart[8*B_DIM*4*NB];   // sinkhorn partial colsums
__device__ int   g_bar[8*B_DIM];            // sinkhorn barriers

// =================== warp-MMA helpers (compute_80-compatible PTX) ===================
__device__ __forceinline__ uint32_t smem_u32(const void* p) {
    uint32_t a;
    asm("{ .reg .u64 t; cvta.to.shared.u64 t, %1; cvt.u32.u64 %0, t; }" : "=r"(a) : "l"(p));
    return a;
}

#define CP_ASYNC16(dst, src) \
    asm volatile("cp.async.cg.shared.global [%0], [%1], 16;" :: "r"(dst), "l"(src))
#define CP_COMMIT() asm volatile("cp.async.commit_group;")
#define CP_WAIT3()  asm volatile("cp.async.wait_group 3;")
#define CP_WAIT1()  asm volatile("cp.async.wait_group 1;")
#define CP_WAIT0()  asm volatile("cp.async.wait_group 0;")

#define LDSM_X4(r0, r1, r2, r3, addr) \
    asm volatile("ldmatrix.sync.aligned.m8n8.x4.shared.b16 {%0,%1,%2,%3}, [%4];" \
        : "=r"(r0), "=r"(r1), "=r"(r2), "=r"(r3) : "r"(addr))

#define LDSM_X4_T(r0, r1, r2, r3, addr) \
    asm volatile("ldmatrix.sync.aligned.m8n8.x4.trans.shared.b16 {%0,%1,%2,%3}, [%4];" \
        : "=r"(r0), "=r"(r1), "=r"(r2), "=r"(r3) : "r"(addr))

#define MMA16816F16(d, a0, a1, a2, a3, b0, b1) \
    asm volatile("mma.sync.aligned.m16n8k16.row.col.f32.f16.f16.f32 " \
        "{%0,%1,%2,%3}, {%4,%5,%6,%7}, {%8,%9}, {%0,%1,%2,%3};" \
        : "+f"((d)[0]), "+f"((d)[1]), "+f"((d)[2]), "+f"((d)[3]) \
        : "r"(a0), "r"(a1), "r"(a2), "r"(a3), "r"(b0), "r"(b1))

// =================== generic fp16 HMMA GEMM (frozen core) ===================
#define HG_A_ROW 80
#define HG_A_TILE (128*HG_A_ROW)   // 10240
#define HG_BT_ROW 272
#define HG_BT_TILE (32*HG_BT_ROW)  // 8704

template <bool BTRANS, bool BIAS, bool OUT_HALF, bool SPLITK>
__global__ __launch_bounds__(256)
void hgemm_kernel(void* __restrict__ Cv, const __half* __restrict__ A,
                  const __half* __restrict__ B, const float* __restrict__ bias,
                  int M, int N, int K, int lda, float alpha, long sA, long sB, long sC) {
    constexpr int B_TILE = BTRANS ? HG_BT_TILE : HG_A_TILE;
    constexpr int STAGE = HG_A_TILE + B_TILE;
    extern __shared__ char smem[];
    uint32_t sbase = smem_u32(smem);

    int z = blockIdx.z;
    long cofs;
    if (SPLITK) {
        int zb = z >> 1, zs = z & 1;
        A += (long)zb * sA + zs * K;
        B += (long)zb * sB + zs * K;
        cofs = (long)zb * sC;
    } else {
        A += (long)z * sA; B += (long)z * sB;
        cofs = (long)z * sC;
    }

    int tid = threadIdx.x, wid = tid >> 5, lane = tid & 31;
    int bm = blockIdx.y * 128, bn = blockIdx.x * 128;
    int wm = (wid & 1) * 64, wn = (wid >> 1) * 32;

    float acc[4][4][4];
#pragma unroll
    for (int i = 0; i < 4; i++)
#pragma unroll
        for (int j = 0; j < 4; j++)
#pragma unroll
            for (int r = 0; r < 4; r++) acc[i][j][r] = 0.f;

    auto stage_load = [&](int kt, int buf) {
        int k0 = kt * 32;
        uint32_t base = sbase + buf * STAGE;
#pragma unroll
        for (int q = 0; q < 2; q++) {
            int c = tid + q * 256;
            int row = c >> 2, seg = c & 3;
            CP_ASYNC16(base + row * HG_A_ROW + seg * 16,
                       A + (size_t)(bm + row) * lda + k0 + seg * 8);
        }
        if (!BTRANS) {
#pragma unroll
            for (int q = 0; q < 2; q++) {
                int c = tid + q * 256;
                int row = c >> 2, seg = c & 3;
                CP_ASYNC16(base + HG_A_TILE + row * HG_A_ROW + seg * 16,
                           B + (size_t)(bn + row) * lda + k0 + seg * 8);
            }
        } else {
#pragma unroll
            for (int q = 0; q < 2; q++) {
                int c = tid + q * 256;
                int kk = c >> 4, seg = c & 15;
                CP_ASYNC16(base + HG_A_TILE + kk * HG_BT_ROW + seg * 16,
                           B + (size_t)(k0 + kk) * N + bn + seg * 8);
            }
        }
        CP_COMMIT();
    };

    int lrow = lane & 15, lhi = lane >> 4;

    stage_load(0, 0);
    int NKT = K / 32;
    for (int kt = 0; kt < NKT; kt++) {
        if (kt + 1 < NKT) { stage_load(kt + 1, (kt + 1) & 1); CP_WAIT1(); }
        else CP_WAIT0();
        __syncthreads();

        uint32_t base = sbase + (kt & 1) * STAGE;
        uint32_t aS = base, bS = base + HG_A_TILE;

#pragma unroll
        for (int ks = 0; ks < 2; ks++) {
            uint32_t a[4][4], bt[2][4];
#pragma unroll
            for (int mt = 0; mt < 4; mt++) {
                uint32_t off = (wm + mt * 16 + lrow) * HG_A_ROW + (ks * 16 + lhi * 8) * 2;
                LDSM_X4(a[mt][0], a[mt][1], a[mt][2], a[mt][3], aS + off);
            }
            if (!BTRANS) {
#pragma unroll
                for (int nt = 0; nt < 2; nt++) {
                    uint32_t off = (wn + nt * 16 + lrow) * HG_A_ROW + (ks * 16 + lhi * 8) * 2;
                    LDSM_X4(bt[nt][0], bt[nt][1], bt[nt][2], bt[nt][3], bS + off);
                }
#pragma unroll
                for (int mt = 0; mt < 4; mt++)
#pragma unroll
                    for (int j = 0; j < 4; j++) {
                        int nt = j >> 1, hi = j & 1;
                        MMA16816F16(acc[mt][j], a[mt][0], a[mt][1], a[mt][2], a[mt][3],
                                    bt[nt][hi], bt[nt][hi + 2]);
                    }
            } else {
#pragma unroll
                for (int ng = 0; ng < 2; ng++) {
                    uint32_t off = (ks * 16 + lrow) * HG_BT_ROW + (wn + ng * 16 + lhi * 8) * 2;
                    LDSM_X4_T(bt[ng][0], bt[ng][1], bt[ng][2], bt[ng][3], bS + off);
                }
#pragma unroll
                for (int mt = 0; mt < 4; mt++)
#pragma unroll
                    for (int j = 0; j < 4; j++) {
                        int ng = j >> 1, hi = j & 1;
                        MMA16816F16(acc[mt][j], a[mt][0], a[mt][1], a[mt][2], a[mt][3],
                                    bt[ng][hi * 2], bt[ng][hi * 2 + 1]);
                    }
            }
        }
        __syncthreads();
    }

    // ---- epilogue ----
#pragma unroll
    for (int mt = 0; mt < 4; mt++) {
        int m0 = bm + wm + mt * 16 + (lane >> 2);
        int m1 = m0 + 8;
#pragma unroll
        for (int j = 0; j < 4; j++) {
            int n = bn + wn + j * 8 + (lane & 3) * 2;
            float v00 = acc[mt][j][0] * alpha, v01 = acc[mt][j][1] * alpha;
            float v10 = acc[mt][j][2] * alpha, v11 = acc[mt][j][3] * alpha;
            if (BIAS) {
                float b0 = bias[(long)blockIdx.z * N + n], b1 = bias[(long)blockIdx.z * N + n + 1];
                v00 += b0; v01 += b1; v10 += b0; v11 += b1;
            }
            if (SPLITK) {
                float* C = (float*)Cv + cofs;
                atomicAdd(C + (size_t)m0 * N + n, v00);
                atomicAdd(C + (size_t)m0 * N + n + 1, v01);
                atomicAdd(C + (size_t)m1 * N + n, v10);
                atomicAdd(C + (size_t)m1 * N + n + 1, v11);
            } else if (OUT_HALF) {
                __half* C = (__half*)Cv + cofs;
                *(__half2*)(C + (size_t)m0 * N + n) = __floats2half2_rn(v00, v01);
                *(__half2*)(C + (size_t)m1 * N + n) = __floats2half2_rn(v10, v11);
            } else {
                float* C = (float*)Cv + cofs;
                *(float2*)(C + (size_t)m0 * N + n) = make_float2(v00, v01);
                *(float2*)(C + (size_t)m1 * N + n) = make_float2(v10, v11);
            }
        }
    }
}

// =================== Y GEMM: Y = Vh @ wvoh^T, fp16 out (frozen hmma core) ===================
#define KC 32
#define ROW_B 80
#define A_TILE_B (128*ROW_B)
#define B_TILE_B (256*ROW_B)
#define STAGE_B (A_TILE_B + B_TILE_B)
#define HMMA_SMEM (4*STAGE_B)

__global__ __launch_bounds__(256, 1)
void hmma_y_kernel(__half* __restrict__ Y,
                   const __half* __restrict__ Ah, const __half* __restrict__ Bh) {
    extern __shared__ char smem[];
    uint32_t sbase = smem_u32(smem);

    int tid = threadIdx.x, wid = tid >> 5, lane = tid & 31;
    int bm = blockIdx.y * 128, bn = blockIdx.x * 256;
    int wm = (wid & 1) * 64, wn = (wid >> 1) * 64;

    const __half* Ag = Ah + (size_t)bm * 1024;
    const __half* Bg = Bh + (size_t)bn * 1024;

    float acc[4][8][4];
#pragma unroll
    for (int i = 0; i < 4; i++)
#pragma unroll
        for (int j = 0; j < 8; j++)
#pragma unroll
            for (int r = 0; r < 4; r++) acc[i][j][r] = 0.f;

    auto stage_load = [&](int kt, int buf) {
        int k0 = kt * KC;
        uint32_t base = sbase + buf * STAGE_B;
#pragma unroll
        for (int q = 0; q < 2; q++) {
            int c = tid + q * 256;
            int row = c >> 2, seg = c & 3;
            CP_ASYNC16(base + row * ROW_B + seg * 16,
                       Ag + (size_t)row * 1024 + k0 + seg * 8);
        }
#pragma unroll
        for (int q = 0; q < 4; q++) {
            int c = tid + q * 256;
            int row = c >> 2, seg = c & 3;
            CP_ASYNC16(base + A_TILE_B + row * ROW_B + seg * 16,
                       Bg + (size_t)row * 1024 + k0 + seg * 8);
        }
    };

    int lrow = lane & 15, lkseg = (lane >> 4) * 8;

    stage_load(0, 0); CP_COMMIT();
    stage_load(1, 1); CP_COMMIT();
    stage_load(2, 2); CP_COMMIT();

    const int NKT = 1024 / KC;
    for (int kt = 0; kt < NKT; kt++) {
        if (kt + 3 < NKT) stage_load(kt + 3, (kt + 3) & 3);
        CP_COMMIT();
        CP_WAIT3();
        __syncthreads();

        uint32_t base = sbase + (kt & 3) * STAGE_B;
        uint32_t aS = base, bS = base + A_TILE_B;

#pragma unroll
        for (int ks = 0; ks < KC / 16; ks++) {
            int kb = (ks * 16 + lkseg) * 2;
            uint32_t a[4][4], b[4][4];
#pragma unroll
            for (int mt = 0; mt < 4; mt++) {
                uint32_t off = (wm + mt * 16 + lrow) * ROW_B + kb;
                LDSM_X4(a[mt][0], a[mt][1], a[mt][2], a[mt][3], aS + off);
            }
#pragma unroll
            for (int nt = 0; nt < 4; nt++) {
                uint32_t off = (wn + nt * 16 + lrow) * ROW_B + kb;
                LDSM_X4(b[nt][0], b[nt][1], b[nt][2], b[nt][3], bS + off);
            }
#pragma unroll
            for (int mt = 0; mt < 4; mt++) {
#pragma unroll
                for (int j = 0; j < 8; j++) {
                    int nt = j >> 1, hi = j & 1;
                    MMA16816F16(acc[mt][j], a[mt][0], a[mt][1], a[mt][2], a[mt][3],
                                b[nt][hi], b[nt][hi + 2]);
                }
            }
        }
        __syncthreads();
    }

#pragma unroll
    for (int mt = 0; mt < 4; mt++) {
        int m0 = bm + wm + mt * 16 + (lane >> 2);
        int m1 = m0 + 8;
#pragma unroll
        for (int j = 0; j < 8; j++) {
            int n = bn + wn + j * 8 + (lane & 3) * 2;
            *(__half2*)(Y + (size_t)m0 * 1024 + n) = __floats2half2_rn(acc[mt][j][0], acc[mt][j][1]);
            *(__half2*)(Y + (size_t)m1 * 1024 + n) = __floats2half2_rn(acc[mt][j][2], acc[mt][j][3]);
        }
    }
}

// =================== final mix: out = P @ Y + bo + rowsum*bvo (zmix core, fp32 epilogue) ===
#define ZA_ROW_B 80
#define ZA_TILE_B (128*ZA_ROW_B)
#define ZB_ROW_B 272
#define ZB_TILE_B (32*ZB_ROW_B)
#define ZSTAGE_B (ZA_TILE_B + ZB_TILE_B)
#define ZSMEM (2*ZSTAGE_B)

__global__ __launch_bounds__(256, 1)
void out_mix_kernel(const __half* __restrict__ Ph, const __half* __restrict__ Yh,
                    float* __restrict__ out, const float* __restrict__ bo,
                    const float* __restrict__ bvo, const float* __restrict__ rowsum) {
    extern __shared__ char smem[];
    uint32_t sbase = smem_u32(smem);

    int tid = threadIdx.x, wid = tid >> 5, lane = tid & 31;
    int b = blockIdx.z;
    int pos = blockIdx.y >> 1, mt0 = blockIdx.y & 1;
    int bm = mt0 * 128, bn = blockIdx.x * 128;
    int wm = (wid & 1) * 64, wn = (wid >> 1) * 32;

    const __half* Ag = Ph + (size_t)b * (NB * NB) + (size_t)bm * 256;

    float acc[4][4][4];
#pragma unroll
    for (int i = 0; i < 4; i++)
#pragma unroll
        for (int j = 0; j < 4; j++)
#pragma unroll
            for (int r = 0; r < 4; r++) acc[i][j][r] = 0.f;

    auto stage_load = [&](int kt, int buf) {
        int k0 = kt * 32;
        uint32_t base = sbase + buf * ZSTAGE_B;
#pragma unroll
        for (int q = 0; q < 2; q++) {
            int c = tid + q * 256;
            int row = c >> 2, seg = c & 3;
            CP_ASYNC16(base + row * ZA_ROW_B + seg * 16,
                       Ag + (size_t)row * 256 + k0 + seg * 8);
        }
#pragma unroll
        for (int q = 0; q < 2; q++) {
            int c = tid + q * 256;
            int kk = c >> 4, seg = c & 15;
            size_t grow = (size_t)(16 * (k0 + kk) + pos) * (B_DIM * E_DIM) + b * E_DIM + bn;
            CP_ASYNC16(base + ZA_TILE_B + kk * ZB_ROW_B + seg * 16, Yh + grow + seg * 8);
        }
        CP_COMMIT();
    };

    int lrow = lane & 15, lhi = lane >> 4;

    stage_load(0, 0);
    for (int kt = 0; kt < 8; kt++) {
        if (kt + 1 < 8) { stage_load(kt + 1, (kt + 1) & 1); CP_WAIT1(); }
        else CP_WAIT0();
        __syncthreads();

        uint32_t base = sbase + (kt & 1) * ZSTAGE_B;
        uint32_t aS = base, bS = base + ZA_TILE_B;

#pragma unroll
        for (int ks = 0; ks < 2; ks++) {
            uint32_t a[4][4], bt[2][4];
#pragma unroll
            for (int mt = 0; mt < 4; mt++) {
                uint32_t off = (wm + mt * 16 + lrow) * ZA_ROW_B + (ks * 16 + lhi * 8) * 2;
                LDSM_X4(a[mt][0], a[mt][1], a[mt][2], a[mt][3], aS + off);
            }
#pragma unroll
            for (int ng = 0; ng < 2; ng++) {
                uint32_t off = (ks * 16 + lrow) * ZB_ROW_B + (wn + ng * 16 + lhi * 8) * 2;
                LDSM_X4_T(bt[ng][0], bt[ng][1], bt[ng][2], bt[ng][3], bS + off);
            }
#pragma unroll
            for (int mt = 0; mt < 4; mt++) {
#pragma unroll
                for (int j = 0; j < 4; j++) {
                    int ng = j >> 1, hi = j & 1;
                    MMA16816F16(acc[mt][j], a[mt][0], a[mt][1], a[mt][2], a[mt][3],
                                bt[ng][hi * 2], bt[ng][hi * 2 + 1]);
                }
            }
        }
        __syncthreads();
    }

    // epilogue: out[((tb*16+pos)*8+b)*1024 + e] = acc + bo[e] + rowsum[b*256+tb]*bvo[e]
#pragma unroll
    for (int mt = 0; mt < 4; mt++) {
        int tb0 = bm + wm + mt * 16 + (lane >> 2);
        int tb1 = tb0 + 8;
        float rs0 = rowsum[b * 256 + tb0];
        float rs1 = rowsum[b * 256 + tb1];
        size_t r0 = ((size_t)(tb0 * 16 + pos) * 8 + b) * 1024;
        size_t r1 = ((size_t)(tb1 * 16 + pos) * 8 + b) * 1024;
#pragma unroll
        for (int j = 0; j < 4; j++) {
            int e = bn + wn + j * 8 + (lane & 3) * 2;
            float b0 = bo[e], b1 = bo[e + 1], v0 = bvo[e], v1 = bvo[e + 1];
            *(float2*)(out + r0 + e) =
                make_float2(acc[mt][j][0] + b0 + rs0 * v0, acc[mt][j][1] + b1 + rs0 * v1);
            *(float2*)(out + r1 + e) =
                make_float2(acc[mt][j][2] + b0 + rs1 * v0, acc[mt][j][3] + b1 + rs1 * v1);
        }
    }
}

// =================== elementwise / small kernels ===================
__global__ void bucket_mean_h_kernel(const float* __restrict__ X, __half* __restrict__ out) {
    int o = blockIdx.x * 256 + threadIdx.x;
    int e = o & (E_DIM - 1);
    int m = o >> 10;
    int b = m >> 8;
    int i = m & 255;
    const float* src = X + (size_t)(i * BUCKET) * (B_DIM * E_DIM) + b * E_DIM + e;
    float s = 0.f;
#pragma unroll
    for (int pos = 0; pos < BUCKET; pos++) s += src[(size_t)pos * (B_DIM * E_DIM)];
    out[o] = __float2half_rn(s * (1.0f / BUCKET));
}

__global__ void kpmb_kernel(const unsigned char* __restrict__ mask, int* __restrict__ kpmb) {
    int j = blockIdx.x * 256 + threadIdx.x;
    if (j >= B_DIM * NB) return;
    int b = j >> 8, s = j & 255;
    const unsigned char* m = mask + b * S_DIM + s * BUCKET;
    int all = 1;
#pragma unroll
    for (int t = 0; t < BUCKET; t++) all &= (m[t] != 0);
    kpmb[j] = all;
}

__global__ void bvo_kernel(const float* __restrict__ Wo, const float* __restrict__ bv,
                           float* __restrict__ bvo) {
    int g = blockIdx.x * 8 + (threadIdx.x >> 5);
    int l = threadIdx.x & 31;
    if (g >= E_DIM) return;
    float s = 0.f;
    for (int k = l; k < E_DIM; k += 32) s += Wo[(size_t)g * E_DIM + k] * bv[k];
#pragma unroll
    for (int off = 16; off; off >>= 1) s += __shfl_xor_sync(0xffffffffu, s, off);
    if (l == 0) bvo[g] = s;
}

__global__ void cvt8_kernel(const float* __restrict__ X, __half* __restrict__ H) {
    size_t i = ((size_t)blockIdx.x * 256 + threadIdx.x) * 8;
    float4 a = *(const float4*)(X + i);
    float4 c = *(const float4*)(X + i + 4);
    __half2 h[4];
    h[0] = __floats2half2_rn(a.x, a.y);
    h[1] = __floats2half2_rn(a.z, a.w);
    h[2] = __floats2half2_rn(c.x, c.y);
    h[3] = __floats2half2_rn(c.z, c.w);
    *(uint4*)(H + i) = *(uint4*)h;
}

__global__ void cvt8x4_kernel(const float* __restrict__ W0, const float* __restrict__ W1,
                              const float* __restrict__ W2, const float* __restrict__ W3,
                              __half* __restrict__ H0, __half* __restrict__ H1,
                              __half* __restrict__ H2, __half* __restrict__ H3) {
    const float* X = (blockIdx.y == 0) ? W0 : (blockIdx.y == 1) ? W1 : (blockIdx.y == 2) ? W2 : W3;
    __half* H = (blockIdx.y == 0) ? H0 : (blockIdx.y == 1) ? H1 : (blockIdx.y == 2) ? H2 : H3;
    size_t i = ((size_t)blockIdx.x * 256 + threadIdx.x) * 8;
    float4 a = *(const float4*)(X + i);
    float4 c = *(const float4*)(X + i + 4);
    __half2 h[4];
    h[0] = __floats2half2_rn(a.x, a.y);
    h[1] = __floats2half2_rn(a.z, a.w);
    h[2] = __floats2half2_rn(c.x, c.y);
    h[3] = __floats2half2_rn(c.z, c.w);
    *(uint4*)(H + i) = *(uint4*)h;
}

// ---------------- sinkhorn: 4 CTAs per batch (R15 version) ----------------
__global__ __launch_bounds__(1024, 1)
void sinkhorn_kernel(float* __restrict__ la, const int* __restrict__ kpmb,
                     __half* __restrict__ ph, float* __restrict__ rowsum,
                     float* __restrict__ colpart, int* __restrict__ bar) {
    int b = blockIdx.x >> 2, part = blockIdx.x & 3;
    float* base = la + b * (NB * NB);
    int tid = threadIdx.x, w = tid >> 5, l = tid & 31;
    __shared__ float sh[32 * 256];
    __shared__ float colv[256];
    __shared__ int mflag[256];
    if (tid < 256) { colv[tid] = 0.f; mflag[tid] = kpmb[b * 256 + tid]; }
    __syncthreads();

    int cf[8];
#pragma unroll
    for (int ci = 0; ci < 8; ci++) cf[ci] = mflag[ci * 32 + l];

    for (int it = 0; it < 8; it++) {
        float cv[8], cs[8];
#pragma unroll
        for (int ci = 0; ci < 8; ci++) { cv[ci] = colv[ci * 32 + l]; cs[ci] = 0.f; }
#pragma unroll
        for (int ri = 0; ri < 2; ri++) {
            int r = part * 64 + w * 2 + ri;
            float v[8];
#pragma unroll
            for (int ci = 0; ci < 8; ci++) v[ci] = base[r * 256 + ci * 32 + l] - cv[ci];
            float m = 0.f;
            if (it == 0) {
                int rf = mflag[r];
#pragma unroll
                for (int ci = 0; ci < 8; ci++) if (rf != cf[ci]) v[ci] = -1e30f;
                m = v[0];
#pragma unroll
                for (int ci = 1; ci < 8; ci++) m = fmaxf(m, v[ci]);
#pragma unroll
                for (int off = 16; off; off >>= 1) m = fmaxf(m, __shfl_xor_sync(0xffffffffu, m, off));
            }
            float e[8];
            float s = 0.f;
#pragma unroll
            for (int ci = 0; ci < 8; ci++) { e[ci] = __expf(v[ci] - m); s += e[ci]; }
#pragma unroll
            for (int off = 16; off; off >>= 1) s += __shfl_xor_sync(0xffffffffu, s, off);
            float lse = m + __logf(s);
            float inv = __fdividef(1.0f, s);
#pragma unroll
            for (int ci = 0; ci < 8; ci++) {
                base[r * 256 + ci * 32 + l] = v[ci] - lse;
                cs[ci] += e[ci] * inv;
            }
        }
#pragma unroll
        for (int ci = 0; ci < 8; ci++) sh[w * 256 + ci * 32 + l] = cs[ci];
        __syncthreads();
        if (tid < 256) {
            float s = 0.f;
#pragma unroll 4
            for (int ww = 0; ww < 32; ww++) s += sh[ww * 256 + tid];
            colpart[(((it * B_DIM + b) * 4 + part) << 8) + tid] = s;
        }
        __threadfence();
        __syncthreads();
        if (tid == 0) {
            int* pb = bar + it * B_DIM + b;
            atomicAdd(pb, 1);
            while (atomicAdd(pb, 0) < 4) { }
        }
        __syncthreads();
        if (tid < 256) {
            const float* cp = colpart + (((it * B_DIM + b) * 4) << 8) + tid;
            float s = __ldcg(cp) + __ldcg(cp + 256) + __ldcg(cp + 512) + __ldcg(cp + 768);
            colv[tid] = __logf(s);
        }
        __syncthreads();
    }

    float cv[8];
#pragma unroll
    for (int ci = 0; ci < 8; ci++) cv[ci] = colv[ci * 32 + l];
#pragma unroll
    for (int ri = 0; ri < 2; ri++) {
        int r = part * 64 + w * 2 + ri;
        float s = 0.f;
#pragma unroll
        for (int ci = 0; ci < 8; ci++) {
            float e = __expf(base[r * 256 + ci * 32 + l] - cv[ci]);
            ph[b * (NB * NB) + r * 256 + ci * 32 + l] = __float2half_rn(e);
            s += e;
        }
#pragma unroll
        for (int off = 16; off; off >>= 1) s += __shfl_xor_sync(0xffffffffu, s, off);
        if (l == 0) rowsum[b * 256 + r] = s;
    }
}

// ---------------- launch: Y GEMM off-path, fully overlapped ----------------
extern "C" void kernel_launch(void* const* d_in, const int* in_sizes, int n_in,
                              void* d_out, int out_size) {
    const float* query = (const float*)d_in[0];
    const float* key_t = (const float*)d_in[1];
    const float* value = (const float*)d_in[2];
    const unsigned char* kpm = (const unsigned char*)d_in[3];
    const float* Wq = (const float*)d_in[4];
    const float* bq = (const float*)d_in[5];
    const float* Wk = (const float*)d_in[6];
    const float* bk = (const float*)d_in[7];
    const float* Wv = (const float*)d_in[8];
    const float* bv = (const float*)d_in[9];
    const float* Wo = (const float*)d_in[10];
    const float* bo = (const float*)d_in[11];
    float* out = (float*)d_out;

    float *la, *rowsum, *bvo, *bqk, *colpart;
    __half *qkmh, *qkbh, *Wqkh, *Wvh, *Woh, *ph, *vh, *yh, *wvoh;
    int *kpmb, *bar;
    cudaGetSymbolAddress((void**)&qkmh, g_qkmh);
    cudaGetSymbolAddress((void**)&qkbh, g_qkbh);
    cudaGetSymbolAddress((void**)&Wqkh, g_Wqkh);
    cudaGetSymbolAddress((void**)&Wvh, g_Wvh);
    cudaGetSymbolAddress((void**)&Woh, g_Woh);
    cudaGetSymbolAddress((void**)&bqk, g_bqk);
    cudaGetSymbolAddress((void**)&la, g_la);
    cudaGetSymbolAddress((void**)&ph, g_ph);
    cudaGetSymbolAddress((void**)&rowsum, g_rowsum);
    cudaGetSymbolAddress((void**)&kpmb, g_kpmb);
    cudaGetSymbolAddress((void**)&bvo, g_bvo);
    cudaGetSymbolAddress((void**)&vh, g_vh);
    cudaGetSymbolAddress((void**)&yh, g_yh);
    cudaGetSymbolAddress((void**)&wvoh, g_wvoh);
    cudaGetSymbolAddress((void**)&colpart, g_colpart);
    cudaGetSymbolAddress((void**)&bar, g_bar);

    static cudaStream_t s1 = nullptr, s2 = nullptr;
    static cudaEvent_t evRoot, evW, evV, evY;
    static bool init_done = false;
    if (!init_done) {
        cudaFuncSetAttribute(hmma_y_kernel, cudaFuncAttributeMaxDynamicSharedMemorySize, HMMA_SMEM);
        cudaStreamCreateWithFlags(&s1, cudaStreamNonBlocking);
        cudaStreamCreateWithFlags(&s2, cudaStreamNonBlocking);
        cudaEventCreateWithFlags(&evRoot, cudaEventDisableTiming);
        cudaEventCreateWithFlags(&evW, cudaEventDisableTiming);
        cudaEventCreateWithFlags(&evV, cudaEventDisableTiming);
        cudaEventCreateWithFlags(&evY, cudaEventDisableTiming);
        init_done = true;
    }

    const int HG_SMEM_N = 2 * (HG_A_TILE + HG_A_TILE);   // 40960
    const int HG_SMEM_T = 2 * (HG_A_TILE + HG_BT_TILE);  // 37888
    const int EE = E_DIM * E_DIM;

    // ---- fork side streams ----
    cudaEventRecord(evRoot, 0);
    cudaStreamWaitEvent(s1, evRoot, 0);
    cudaStreamWaitEvent(s2, evRoot, 0);

    // s1: value -> fp16 (feeds Y GEMM)
    cvt8_kernel<<<(S_DIM * B_DIM * E_DIM) / 2048, 256, 0, s1>>>(value, vh);
    cudaEventRecord(evV, s1);

    // s2: weight converts -> wvo -> bvo -> (wait evV) -> Y GEMM
    cvt8x4_kernel<<<dim3(EE / 2048, 4), 256, 0, s2>>>(Wq, Wk, Wv, Wo,
                                                      Wqkh, Wqkh + EE, Wvh, Woh);
    cudaEventRecord(evW, s2);
    hgemm_kernel<true, false, true, false><<<dim3(8, 8, 1), 256, HG_SMEM_T, s2>>>(
        wvoh, Woh, Wvh, nullptr, 1024, 1024, 1024, 1024, 1.0f, 0, 0, 0);
    bvo_kernel<<<128, 256, 0, s2>>>(Wo, bv, bvo);
    cudaStreamWaitEvent(s2, evV, 0);
    hmma_y_kernel<<<dim3(4, 256, 1), 256, HMMA_SMEM, s2>>>(yh, vh, wvoh);
    cudaEventRecord(evY, s2);

    // main: bias pack, zero la + barriers, mask flags, bucket means
    cudaMemcpyAsync(bqk, bq, E_DIM * sizeof(float), cudaMemcpyDeviceToDevice, 0);
    cudaMemcpyAsync(bqk + E_DIM, bk, E_DIM * sizeof(float), cudaMemcpyDeviceToDevice, 0);
    cudaMemsetAsync(la, 0, (size_t)B_DIM * NB * NB * sizeof(float), 0);
    cudaMemsetAsync(bar, 0, 8 * B_DIM * sizeof(int), 0);
    kpmb_kernel<<<8, 256>>>(kpm, kpmb);
    bucket_mean_h_kernel<<<(B_DIM * NB * E_DIM) / 256, 256>>>(query, qkmh);
    bucket_mean_h_kernel<<<(B_DIM * NB * E_DIM) / 256, 256>>>(key_t, qkmh + QK_STRIDE);

    // main: batched Q+K projection (needs weight cvt)
    cudaStreamWaitEvent(0, evW, 0);
    hgemm_kernel<false, true, true, false><<<dim3(8, 16, 2), 256, HG_SMEM_N>>>(
        qkbh, qkmh, Wqkh, bqk, 2048, 1024, 1024, 1024, 1.0f,
        (long)QK_STRIDE, (long)EE, (long)QK_STRIDE);

    // main: attn logits split-K x2
    hgemm_kernel<false, false, false, true><<<dim3(2, 2, 2 * B_DIM), 256, HG_SMEM_N>>>(
        la, qkbh, qkbh + QK_STRIDE, nullptr, 256, 256, 512, 1024, ATTN_ALPHA,
        (long)NB * E_DIM, (long)NB * E_DIM, (long)NB * NB);

    // main: sinkhorn (32 CTAs, 4 per batch)
    sinkhorn_kernel<<<32, 1024>>>(la, kpmb, ph, rowsum, colpart, bar);

    // main: final mix out = P @ Y + biases (needs Y)
    cudaStreamWaitEvent(0, evY, 0);
    out_mix_kernel<<<dim3(8, 32, 8), 256, ZSMEM>>>(ph, yh, out, bo, bvo, rowsum);
}

// round 17
// speedup vs baseline: 1.2835x; 1.0390x over previous
#include <cuda_runtime.h>
#include <cuda_bf16.h>
#include <cuda_fp16.h>
#include <math.h>
#include <cstdint>

// ---------------- problem constants ----------------
#define T_DIM 4096
#define S_DIM 4096
#define B_DIM 8
#define E_DIM 1024
#define BUCKET 16
#define NB 256            // T/BUCKET
#define TAU 0.75f
#define ATTN_ALPHA (1.0f/(32.0f*0.75f))
#define QK_STRIDE (B_DIM*NB*E_DIM)   // 2097152

// ---------------- scratch (device globals; no allocation allowed) ----------------
__device__ __half g_qkmh[2*QK_STRIDE];      // bucket means q|k, fp16
__device__ __half g_qkbh[2*QK_STRIDE];      // projected bucket q|k, fp16
__device__ __half g_Wqkh[2*E_DIM*E_DIM];    // Wq|Wk fp16
__device__ __half g_Wvh[E_DIM*E_DIM];
__device__ __half g_Woh[E_DIM*E_DIM];
__device__ float g_bqk[2*E_DIM];            // bq|bk fp32
__device__ float g_la[B_DIM*NB*NB];
__device__ __half g_ph[B_DIM*NB*NB];        // sinkhorn result, fp16
__device__ float g_rowsum[B_DIM*NB];
__device__ int   g_kpmb[B_DIM*NB];
__device__ float g_bvo[E_DIM];              // Wo @ bv
__device__ __half g_vh[S_DIM*B_DIM*E_DIM];  // value in fp16
__device__ __half g_yh[S_DIM*B_DIM*E_DIM];  // Y = V @ wvo^T, fp16 (rows m=s*8+b)
__device__ __half g_wvoh[E_DIM*E_DIM];      // Wo @ Wv in fp16
__device__ float g_colpart[8*B_DIM*4*NB];   // sinkhorn partial colsums
__device__ int   g_bar[8*B_DIM];            // sinkhorn barriers

// =================== warp-MMA helpers (compute_80-compatible PTX) ===================
__device__ __forceinline__ uint32_t smem_u32(const void* p) {
    uint32_t a;
    asm("{ .reg .u64 t; cvta.to.shared.u64 t, %1; cvt.u32.u64 %0, t; }" : "=r"(a) : "l"(p));
    return a;
}

#define CP_ASYNC16(dst, src) \
    asm volatile("cp.async.cg.shared.global [%0], [%1], 16;" :: "r"(dst), "l"(src))
#define CP_COMMIT() asm volatile("cp.async.commit_group;")
#define CP_WAIT3()  asm volatile("cp.async.wait_group 3;")
#define CP_WAIT1()  asm volatile("cp.async.wait_group 1;")
#define CP_WAIT0()  asm volatile("cp.async.wait_group 0;")

#define LDSM_X4(r0, r1, r2, r3, addr) \
    asm volatile("ldmatrix.sync.aligned.m8n8.x4.shared.b16 {%0,%1,%2,%3}, [%4];" \
        : "=r"(r0), "=r"(r1), "=r"(r2), "=r"(r3) : "r"(addr))

#define LDSM_X4_T(r0, r1, r2, r3, addr) \
    asm volatile("ldmatrix.sync.aligned.m8n8.x4.trans.shared.b16 {%0,%1,%2,%3}, [%4];" \
        : "=r"(r0), "=r"(r1), "=r"(r2), "=r"(r3) : "r"(addr))

#define MMA16816F16(d, a0, a1, a2, a3, b0, b1) \
    asm volatile("mma.sync.aligned.m16n8k16.row.col.f32.f16.f16.f32 " \
        "{%0,%1,%2,%3}, {%4,%5,%6,%7}, {%8,%9}, {%0,%1,%2,%3};" \
        : "+f"((d)[0]), "+f"((d)[1]), "+f"((d)[2]), "+f"((d)[3]) \
        : "r"(a0), "r"(a1), "r"(a2), "r"(a3), "r"(b0), "r"(b1))

// =================== generic fp16 HMMA GEMM (frozen core) ===================
#define HG_A_ROW 80
#define HG_A_TILE (128*HG_A_ROW)   // 10240
#define HG_BT_ROW 272
#define HG_BT_TILE (32*HG_BT_ROW)  // 8704

template <bool BTRANS, bool BIAS, bool OUT_HALF, bool SPLITK>
__global__ __launch_bounds__(256)
void hgemm_kernel(void* __restrict__ Cv, const __half* __restrict__ A,
                  const __half* __restrict__ B, const float* __restrict__ bias,
                  int M, int N, int K, int lda, float alpha, long sA, long sB, long sC) {
    constexpr int B_TILE = BTRANS ? HG_BT_TILE : HG_A_TILE;
    constexpr int STAGE = HG_A_TILE + B_TILE;
    extern __shared__ char smem[];
    uint32_t sbase = smem_u32(smem);

    int z = blockIdx.z;
    long cofs;
    if (SPLITK) {
        int zb = z >> 1, zs = z & 1;
        A += (long)zb * sA + zs * K;
        B += (long)zb * sB + zs * K;
        cofs = (long)zb * sC;
    } else {
        A += (long)z * sA; B += (long)z * sB;
        cofs = (long)z * sC;
    }

    int tid = threadIdx.x, wid = tid >> 5, lane = tid & 31;
    int bm = blockIdx.y * 128, bn = blockIdx.x * 128;
    int wm = (wid & 1) * 64, wn = (wid >> 1) * 32;

    float acc[4][4][4];
#pragma unroll
    for (int i = 0; i < 4; i++)
#pragma unroll
        for (int j = 0; j < 4; j++)
#pragma unroll
            for (int r = 0; r < 4; r++) acc[i][j][r] = 0.f;

    auto stage_load = [&](int kt, int buf) {
        int k0 = kt * 32;
        uint32_t base = sbase + buf * STAGE;
#pragma unroll
        for (int q = 0; q < 2; q++) {
            int c = tid + q * 256;
            int row = c >> 2, seg = c & 3;
            CP_ASYNC16(base + row * HG_A_ROW + seg * 16,
                       A + (size_t)(bm + row) * lda + k0 + seg * 8);
        }
        if (!BTRANS) {
#pragma unroll
            for (int q = 0; q < 2; q++) {
                int c = tid + q * 256;
                int row = c >> 2, seg = c & 3;
                CP_ASYNC16(base + HG_A_TILE + row * HG_A_ROW + seg * 16,
                           B + (size_t)(bn + row) * lda + k0 + seg * 8);
            }
        } else {
#pragma unroll
            for (int q = 0; q < 2; q++) {
                int c = tid + q * 256;
                int kk = c >> 4, seg = c & 15;
                CP_ASYNC16(base + HG_A_TILE + kk * HG_BT_ROW + seg * 16,
                           B + (size_t)(k0 + kk) * N + bn + seg * 8);
            }
        }
        CP_COMMIT();
    };

    int lrow = lane & 15, lhi = lane >> 4;

    stage_load(0, 0);
    int NKT = K / 32;
    for (int kt = 0; kt < NKT; kt++) {
        if (kt + 1 < NKT) { stage_load(kt + 1, (kt + 1) & 1); CP_WAIT1(); }
        else CP_WAIT0();
        __syncthreads();

        uint32_t base = sbase + (kt & 1) * STAGE;
        uint32_t aS = base, bS = base + HG_A_TILE;

#pragma unroll
        for (int ks = 0; ks < 2; ks++) {
            uint32_t a[4][4], bt[2][4];
#pragma unroll
            for (int mt = 0; mt < 4; mt++) {
                uint32_t off = (wm + mt * 16 + lrow) * HG_A_ROW + (ks * 16 + lhi * 8) * 2;
                LDSM_X4(a[mt][0], a[mt][1], a[mt][2], a[mt][3], aS + off);
            }
            if (!BTRANS) {
#pragma unroll
                for (int nt = 0; nt < 2; nt++) {
                    uint32_t off = (wn + nt * 16 + lrow) * HG_A_ROW + (ks * 16 + lhi * 8) * 2;
                    LDSM_X4(bt[nt][0], bt[nt][1], bt[nt][2], bt[nt][3], bS + off);
                }
#pragma unroll
                for (int mt = 0; mt < 4; mt++)
#pragma unroll
                    for (int j = 0; j < 4; j++) {
                        int nt = j >> 1, hi = j & 1;
                        MMA16816F16(acc[mt][j], a[mt][0], a[mt][1], a[mt][2], a[mt][3],
                                    bt[nt][hi], bt[nt][hi + 2]);
                    }
            } else {
#pragma unroll
                for (int ng = 0; ng < 2; ng++) {
                    uint32_t off = (ks * 16 + lrow) * HG_BT_ROW + (wn + ng * 16 + lhi * 8) * 2;
                    LDSM_X4_T(bt[ng][0], bt[ng][1], bt[ng][2], bt[ng][3], bS + off);
                }
#pragma unroll
                for (int mt = 0; mt < 4; mt++)
#pragma unroll
                    for (int j = 0; j < 4; j++) {
                        int ng = j >> 1, hi = j & 1;
                        MMA16816F16(acc[mt][j], a[mt][0], a[mt][1], a[mt][2], a[mt][3],
                                    bt[ng][hi * 2], bt[ng][hi * 2 + 1]);
                    }
            }
        }
        __syncthreads();
    }

    // ---- epilogue ----
#pragma unroll
    for (int mt = 0; mt < 4; mt++) {
        int m0 = bm + wm + mt * 16 + (lane >> 2);
        int m1 = m0 + 8;
#pragma unroll
        for (int j = 0; j < 4; j++) {
            int n = bn + wn + j * 8 + (lane & 3) * 2;
            float v00 = acc[mt][j][0] * alpha, v01 = acc[mt][j][1] * alpha;
            float v10 = acc[mt][j][2] * alpha, v11 = acc[mt][j][3] * alpha;
            if (BIAS) {
                float b0 = bias[(long)blockIdx.z * N + n], b1 = bias[(long)blockIdx.z * N + n + 1];
                v00 += b0; v01 += b1; v10 += b0; v11 += b1;
            }
            if (SPLITK) {
                float* C = (float*)Cv + cofs;
                atomicAdd(C + (size_t)m0 * N + n, v00);
                atomicAdd(C + (size_t)m0 * N + n + 1, v01);
                atomicAdd(C + (size_t)m1 * N + n, v10);
                atomicAdd(C + (size_t)m1 * N + n + 1, v11);
            } else if (OUT_HALF) {
                __half* C = (__half*)Cv + cofs;
                *(__half2*)(C + (size_t)m0 * N + n) = __floats2half2_rn(v00, v01);
                *(__half2*)(C + (size_t)m1 * N + n) = __floats2half2_rn(v10, v11);
            } else {
                float* C = (float*)Cv + cofs;
                *(float2*)(C + (size_t)m0 * N + n) = make_float2(v00, v01);
                *(float2*)(C + (size_t)m1 * N + n) = make_float2(v10, v11);
            }
        }
    }
}

// =================== Y GEMM: Y = Vh @ wvoh^T, fp16 out (frozen core; xbase) ===================
#define KC 32
#define ROW_B 80
#define A_TILE_B (128*ROW_B)
#define B_TILE_B (256*ROW_B)
#define STAGE_B (A_TILE_B + B_TILE_B)
#define HMMA_SMEM (4*STAGE_B)

__global__ __launch_bounds__(256, 1)
void hmma_y_kernel(__half* __restrict__ Y,
                   const __half* __restrict__ Ah, const __half* __restrict__ Bh, int xbase) {
    extern __shared__ char smem[];
    uint32_t sbase = smem_u32(smem);

    int tid = threadIdx.x, wid = tid >> 5, lane = tid & 31;
    int bm = blockIdx.y * 128, bn = (blockIdx.x + xbase) * 256;
    int wm = (wid & 1) * 64, wn = (wid >> 1) * 64;

    const __half* Ag = Ah + (size_t)bm * 1024;
    const __half* Bg = Bh + (size_t)bn * 1024;

    float acc[4][8][4];
#pragma unroll
    for (int i = 0; i < 4; i++)
#pragma unroll
        for (int j = 0; j < 8; j++)
#pragma unroll
            for (int r = 0; r < 4; r++) acc[i][j][r] = 0.f;

    auto stage_load = [&](int kt, int buf) {
        int k0 = kt * KC;
        uint32_t base = sbase + buf * STAGE_B;
#pragma unroll
        for (int q = 0; q < 2; q++) {
            int c = tid + q * 256;
            int row = c >> 2, seg = c & 3;
            CP_ASYNC16(base + row * ROW_B + seg * 16,
                       Ag + (size_t)row * 1024 + k0 + seg * 8);
        }
#pragma unroll
        for (int q = 0; q < 4; q++) {
            int c = tid + q * 256;
            int row = c >> 2, seg = c & 3;
            CP_ASYNC16(base + A_TILE_B + row * ROW_B + seg * 16,
                       Bg + (size_t)row * 1024 + k0 + seg * 8);
        }
    };

    int lrow = lane & 15, lkseg = (lane >> 4) * 8;

    stage_load(0, 0); CP_COMMIT();
    stage_load(1, 1); CP_COMMIT();
    stage_load(2, 2); CP_COMMIT();

    const int NKT = 1024 / KC;
    for (int kt = 0; kt < NKT; kt++) {
        if (kt + 3 < NKT) stage_load(kt + 3, (kt + 3) & 3);
        CP_COMMIT();
        CP_WAIT3();
        __syncthreads();

        uint32_t base = sbase + (kt & 3) * STAGE_B;
        uint32_t aS = base, bS = base + A_TILE_B;

#pragma unroll
        for (int ks = 0; ks < KC / 16; ks++) {
            int kb = (ks * 16 + lkseg) * 2;
            uint32_t a[4][4], b[4][4];
#pragma unroll
            for (int mt = 0; mt < 4; mt++) {
                uint32_t off = (wm + mt * 16 + lrow) * ROW_B + kb;
                LDSM_X4(a[mt][0], a[mt][1], a[mt][2], a[mt][3], aS + off);
            }
#pragma unroll
            for (int nt = 0; nt < 4; nt++) {
                uint32_t off = (wn + nt * 16 + lrow) * ROW_B + kb;
                LDSM_X4(b[nt][0], b[nt][1], b[nt][2], b[nt][3], bS + off);
            }
#pragma unroll
            for (int mt = 0; mt < 4; mt++) {
#pragma unroll
                for (int j = 0; j < 8; j++) {
                    int nt = j >> 1, hi = j & 1;
                    MMA16816F16(acc[mt][j], a[mt][0], a[mt][1], a[mt][2], a[mt][3],
                                b[nt][hi], b[nt][hi + 2]);
                }
            }
        }
        __syncthreads();
    }

#pragma unroll
    for (int mt = 0; mt < 4; mt++) {
        int m0 = bm + wm + mt * 16 + (lane >> 2);
        int m1 = m0 + 8;
#pragma unroll
        for (int j = 0; j < 8; j++) {
            int n = bn + wn + j * 8 + (lane & 3) * 2;
            *(__half2*)(Y + (size_t)m0 * 1024 + n) = __floats2half2_rn(acc[mt][j][0], acc[mt][j][1]);
            *(__half2*)(Y + (size_t)m1 * 1024 + n) = __floats2half2_rn(acc[mt][j][2], acc[mt][j][3]);
        }
    }
}

// =================== final mix: out = P @ Y + bo + rowsum*bvo (frozen core; xbase) ===
#define ZA_ROW_B 80
#define ZA_TILE_B (128*ZA_ROW_B)
#define ZB_ROW_B 272
#define ZB_TILE_B (32*ZB_ROW_B)
#define ZSTAGE_B (ZA_TILE_B + ZB_TILE_B)
#define ZSMEM (2*ZSTAGE_B)

__global__ __launch_bounds__(256, 1)
void out_mix_kernel(const __half* __restrict__ Ph, const __half* __restrict__ Yh,
                    float* __restrict__ out, const float* __restrict__ bo,
                    const float* __restrict__ bvo, const float* __restrict__ rowsum,
                    int xbase) {
    extern __shared__ char smem[];
    uint32_t sbase = smem_u32(smem);

    int tid = threadIdx.x, wid = tid >> 5, lane = tid & 31;
    int b = blockIdx.z;
    int pos = blockIdx.y >> 1, mt0 = blockIdx.y & 1;
    int bm = mt0 * 128, bn = (blockIdx.x + xbase) * 128;
    int wm = (wid & 1) * 64, wn = (wid >> 1) * 32;

    const __half* Ag = Ph + (size_t)b * (NB * NB) + (size_t)bm * 256;

    float acc[4][4][4];
#pragma unroll
    for (int i = 0; i < 4; i++)
#pragma unroll
        for (int j = 0; j < 4; j++)
#pragma unroll
            for (int r = 0; r < 4; r++) acc[i][j][r] = 0.f;

    auto stage_load = [&](int kt, int buf) {
        int k0 = kt * 32;
        uint32_t base = sbase + buf * ZSTAGE_B;
#pragma unroll
        for (int q = 0; q < 2; q++) {
            int c = tid + q * 256;
            int row = c >> 2, seg = c & 3;
            CP_ASYNC16(base + row * ZA_ROW_B + seg * 16,
                       Ag + (size_t)row * 256 + k0 + seg * 8);
        }
#pragma unroll
        for (int q = 0; q < 2; q++) {
            int c = tid + q * 256;
            int kk = c >> 4, seg = c & 15;
            size_t grow = (size_t)(16 * (k0 + kk) + pos) * (B_DIM * E_DIM) + b * E_DIM + bn;
            CP_ASYNC16(base + ZA_TILE_B + kk * ZB_ROW_B + seg * 16, Yh + grow + seg * 8);
        }
        CP_COMMIT();
    };

    int lrow = lane & 15, lhi = lane >> 4;

    stage_load(0, 0);
    for (int kt = 0; kt < 8; kt++) {
        if (kt + 1 < 8) { stage_load(kt + 1, (kt + 1) & 1); CP_WAIT1(); }
        else CP_WAIT0();
        __syncthreads();

        uint32_t base = sbase + (kt & 1) * ZSTAGE_B;
        uint32_t aS = base, bS = base + ZA_TILE_B;

#pragma unroll
        for (int ks = 0; ks < 2; ks++) {
            uint32_t a[4][4], bt[2][4];
#pragma unroll
            for (int mt = 0; mt < 4; mt++) {
                uint32_t off = (wm + mt * 16 + lrow) * ZA_ROW_B + (ks * 16 + lhi * 8) * 2;
                LDSM_X4(a[mt][0], a[mt][1], a[mt][2], a[mt][3], aS + off);
            }
#pragma unroll
            for (int ng = 0; ng < 2; ng++) {
                uint32_t off = (ks * 16 + lrow) * ZB_ROW_B + (wn + ng * 16 + lhi * 8) * 2;
                LDSM_X4_T(bt[ng][0], bt[ng][1], bt[ng][2], bt[ng][3], bS + off);
            }
#pragma unroll
            for (int mt = 0; mt < 4; mt++) {
#pragma unroll
                for (int j = 0; j < 4; j++) {
                    int ng = j >> 1, hi = j & 1;
                    MMA16816F16(acc[mt][j], a[mt][0], a[mt][1], a[mt][2], a[mt][3],
                                bt[ng][hi * 2], bt[ng][hi * 2 + 1]);
                }
            }
        }
        __syncthreads();
    }

#pragma unroll
    for (int mt = 0; mt < 4; mt++) {
        int tb0 = bm + wm + mt * 16 + (lane >> 2);
        int tb1 = tb0 + 8;
        float rs0 = rowsum[b * 256 + tb0];
        float rs1 = rowsum[b * 256 + tb1];
        size_t r0 = ((size_t)(tb0 * 16 + pos) * 8 + b) * 1024;
        size_t r1 = ((size_t)(tb1 * 16 + pos) * 8 + b) * 1024;
#pragma unroll
        for (int j = 0; j < 4; j++) {
            int e = bn + wn + j * 8 + (lane & 3) * 2;
            float b0 = bo[e], b1 = bo[e + 1], v0 = bvo[e], v1 = bvo[e + 1];
            *(float2*)(out + r0 + e) =
                make_float2(acc[mt][j][0] + b0 + rs0 * v0, acc[mt][j][1] + b1 + rs0 * v1);
            *(float2*)(out + r1 + e) =
                make_float2(acc[mt][j][2] + b0 + rs1 * v0, acc[mt][j][3] + b1 + rs1 * v1);
        }
    }
}

// =================== elementwise / small kernels ===================
__global__ void bucket_mean_h_kernel(const float* __restrict__ X, __half* __restrict__ out) {
    int o = blockIdx.x * 256 + threadIdx.x;
    int e = o & (E_DIM - 1);
    int m = o >> 10;
    int b = m >> 8;
    int i = m & 255;
    const float* src = X + (size_t)(i * BUCKET) * (B_DIM * E_DIM) + b * E_DIM + e;
    float s = 0.f;
#pragma unroll
    for (int pos = 0; pos < BUCKET; pos++) s += src[(size_t)pos * (B_DIM * E_DIM)];
    out[o] = __float2half_rn(s * (1.0f / BUCKET));
}

__global__ void kpmb_kernel(const unsigned char* __restrict__ mask, int* __restrict__ kpmb) {
    int j = blockIdx.x * 256 + threadIdx.x;
    if (j >= B_DIM * NB) return;
    int b = j >> 8, s = j & 255;
    const unsigned char* m = mask + b * S_DIM + s * BUCKET;
    int all = 1;
#pragma unroll
    for (int t = 0; t < BUCKET; t++) all &= (m[t] != 0);
    kpmb[j] = all;
}

__global__ void bvo_kernel(const float* __restrict__ Wo, const float* __restrict__ bv,
                           float* __restrict__ bvo) {
    int g = blockIdx.x * 8 + (threadIdx.x >> 5);
    int l = threadIdx.x & 31;
    if (g >= E_DIM) return;
    float s = 0.f;
    for (int k = l; k < E_DIM; k += 32) s += Wo[(size_t)g * E_DIM + k] * bv[k];
#pragma unroll
    for (int off = 16; off; off >>= 1) s += __shfl_xor_sync(0xffffffffu, s, off);
    if (l == 0) bvo[g] = s;
}

__global__ void cvt8_kernel(const float* __restrict__ X, __half* __restrict__ H) {
    size_t i = ((size_t)blockIdx.x * 256 + threadIdx.x) * 8;
    float4 a = *(const float4*)(X + i);
    float4 c = *(const float4*)(X + i + 4);
    __half2 h[4];
    h[0] = __floats2half2_rn(a.x, a.y);
    h[1] = __floats2half2_rn(a.z, a.w);
    h[2] = __floats2half2_rn(c.x, c.y);
    h[3] = __floats2half2_rn(c.z, c.w);
    *(uint4*)(H + i) = *(uint4*)h;
}

__global__ void cvt8x4_kernel(const float* __restrict__ W0, const float* __restrict__ W1,
                              const float* __restrict__ W2, const float* __restrict__ W3,
                              __half* __restrict__ H0, __half* __restrict__ H1,
                              __half* __restrict__ H2, __half* __restrict__ H3) {
    const float* X = (blockIdx.y == 0) ? W0 : (blockIdx.y == 1) ? W1 : (blockIdx.y == 2) ? W2 : W3;
    __half* H = (blockIdx.y == 0) ? H0 : (blockIdx.y == 1) ? H1 : (blockIdx.y == 2) ? H2 : H3;
    size_t i = ((size_t)blockIdx.x * 256 + threadIdx.x) * 8;
    float4 a = *(const float4*)(X + i);
    float4 c = *(const float4*)(X + i + 4);
    __half2 h[4];
    h[0] = __floats2half2_rn(a.x, a.y);
    h[1] = __floats2half2_rn(a.z, a.w);
    h[2] = __floats2half2_rn(c.x, c.y);
    h[3] = __floats2half2_rn(c.z, c.w);
    *(uint4*)(H + i) = *(uint4*)h;
}

// ---------------- sinkhorn: 4 CTAs per batch (frozen R15 version) ----------------
__global__ __launch_bounds__(1024, 1)
void sinkhorn_kernel(float* __restrict__ la, const int* __restrict__ kpmb,
                     __half* __restrict__ ph, float* __restrict__ rowsum,
                     float* __restrict__ colpart, int* __restrict__ bar) {
    int b = blockIdx.x >> 2, part = blockIdx.x & 3;
    float* base = la + b * (NB * NB);
    int tid = threadIdx.x, w = tid >> 5, l = tid & 31;
    __shared__ float sh[32 * 256];
    __shared__ float colv[256];
    __shared__ int mflag[256];
    if (tid < 256) { colv[tid] = 0.f; mflag[tid] = kpmb[b * 256 + tid]; }
    __syncthreads();

    int cf[8];
#pragma unroll
    for (int ci = 0; ci < 8; ci++) cf[ci] = mflag[ci * 32 + l];

    for (int it = 0; it < 8; it++) {
        float cv[8], cs[8];
#pragma unroll
        for (int ci = 0; ci < 8; ci++) { cv[ci] = colv[ci * 32 + l]; cs[ci] = 0.f; }
#pragma unroll
        for (int ri = 0; ri < 2; ri++) {
            int r = part * 64 + w * 2 + ri;
            float v[8];
#pragma unroll
            for (int ci = 0; ci < 8; ci++) v[ci] = base[r * 256 + ci * 32 + l] - cv[ci];
            float m = 0.f;
            if (it == 0) {
                int rf = mflag[r];
#pragma unroll
                for (int ci = 0; ci < 8; ci++) if (rf != cf[ci]) v[ci] = -1e30f;
                m = v[0];
#pragma unroll
                for (int ci = 1; ci < 8; ci++) m = fmaxf(m, v[ci]);
#pragma unroll
                for (int off = 16; off; off >>= 1) m = fmaxf(m, __shfl_xor_sync(0xffffffffu, m, off));
            }
            float e[8];
            float s = 0.f;
#pragma unroll
            for (int ci = 0; ci < 8; ci++) { e[ci] = __expf(v[ci] - m); s += e[ci]; }
#pragma unroll
            for (int off = 16; off; off >>= 1) s += __shfl_xor_sync(0xffffffffu, s, off);
            float lse = m + __logf(s);
            float inv = __fdividef(1.0f, s);
#pragma unroll
            for (int ci = 0; ci < 8; ci++) {
                base[r * 256 + ci * 32 + l] = v[ci] - lse;
                cs[ci] += e[ci] * inv;
            }
        }
#pragma unroll
        for (int ci = 0; ci < 8; ci++) sh[w * 256 + ci * 32 + l] = cs[ci];
        __syncthreads();
        if (tid < 256) {
            float s = 0.f;
#pragma unroll 4
            for (int ww = 0; ww < 32; ww++) s += sh[ww * 256 + tid];
            colpart[(((it * B_DIM + b) * 4 + part) << 8) + tid] = s;
        }
        __threadfence();
        __syncthreads();
        if (tid == 0) {
            int* pb = bar + it * B_DIM + b;
            atomicAdd(pb, 1);
            while (atomicAdd(pb, 0) < 4) { }
        }
        __syncthreads();
        if (tid < 256) {
            const float* cp = colpart + (((it * B_DIM + b) * 4) << 8) + tid;
            float s = __ldcg(cp) + __ldcg(cp + 256) + __ldcg(cp + 512) + __ldcg(cp + 768);
            colv[tid] = __logf(s);
        }
        __syncthreads();
    }

    float cv[8];
#pragma unroll
    for (int ci = 0; ci < 8; ci++) cv[ci] = colv[ci * 32 + l];
#pragma unroll
    for (int ri = 0; ri < 2; ri++) {
        int r = part * 64 + w * 2 + ri;
        float s = 0.f;
#pragma unroll
        for (int ci = 0; ci < 8; ci++) {
            float e = __expf(base[r * 256 + ci * 32 + l] - cv[ci]);
            ph[b * (NB * NB) + r * 256 + ci * 32 + l] = __float2half_rn(e);
            s += e;
        }
#pragma unroll
        for (int off = 16; off; off >>= 1) s += __shfl_xor_sync(0xffffffffu, s, off);
        if (l == 0) rowsum[b * 256 + r] = s;
    }
}

// ---------------- launch: Y N-halves pipelined against mix e-halves ----------------
extern "C" void kernel_launch(void* const* d_in, const int* in_sizes, int n_in,
                              void* d_out, int out_size) {
    const float* query = (const float*)d_in[0];
    const float* key_t = (const float*)d_in[1];
    const float* value = (const float*)d_in[2];
    const unsigned char* kpm = (const unsigned char*)d_in[3];
    const float* Wq = (const float*)d_in[4];
    const float* bq = (const float*)d_in[5];
    const float* Wk = (const float*)d_in[6];
    const float* bk = (const float*)d_in[7];
    const float* Wv = (const float*)d_in[8];
    const float* bv = (const float*)d_in[9];
    const float* Wo = (const float*)d_in[10];
    const float* bo = (const float*)d_in[11];
    float* out = (float*)d_out;

    float *la, *rowsum, *bvo, *bqk, *colpart;
    __half *qkmh, *qkbh, *Wqkh, *Wvh, *Woh, *ph, *vh, *yh, *wvoh;
    int *kpmb, *bar;
    cudaGetSymbolAddress((void**)&qkmh, g_qkmh);
    cudaGetSymbolAddress((void**)&qkbh, g_qkbh);
    cudaGetSymbolAddress((void**)&Wqkh, g_Wqkh);
    cudaGetSymbolAddress((void**)&Wvh, g_Wvh);
    cudaGetSymbolAddress((void**)&Woh, g_Woh);
    cudaGetSymbolAddress((void**)&bqk, g_bqk);
    cudaGetSymbolAddress((void**)&la, g_la);
    cudaGetSymbolAddress((void**)&ph, g_ph);
    cudaGetSymbolAddress((void**)&rowsum, g_rowsum);
    cudaGetSymbolAddress((void**)&kpmb, g_kpmb);
    cudaGetSymbolAddress((void**)&bvo, g_bvo);
    cudaGetSymbolAddress((void**)&vh, g_vh);
    cudaGetSymbolAddress((void**)&yh, g_yh);
    cudaGetSymbolAddress((void**)&wvoh, g_wvoh);
    cudaGetSymbolAddress((void**)&colpart, g_colpart);
    cudaGetSymbolAddress((void**)&bar, g_bar);

    static cudaStream_t s1 = nullptr, s2 = nullptr;
    static cudaEvent_t evRoot, evW, evV, evY0, evY1;
    static bool init_done = false;
    if (!init_done) {
        cudaFuncSetAttribute(hmma_y_kernel, cudaFuncAttributeMaxDynamicSharedMemorySize, HMMA_SMEM);
        int prLow, prHigh;
        cudaDeviceGetStreamPriorityRange(&prLow, &prHigh);
        cudaStreamCreateWithFlags(&s1, cudaStreamNonBlocking);
        cudaStreamCreateWithPriority(&s2, cudaStreamNonBlocking, prHigh);  // Y chain: high prio
        cudaEventCreateWithFlags(&evRoot, cudaEventDisableTiming);
        cudaEventCreateWithFlags(&evW, cudaEventDisableTiming);
        cudaEventCreateWithFlags(&evV, cudaEventDisableTiming);
        cudaEventCreateWithFlags(&evY0, cudaEventDisableTiming);
        cudaEventCreateWithFlags(&evY1, cudaEventDisableTiming);
        init_done = true;
    }

    const int HG_SMEM_N = 2 * (HG_A_TILE + HG_A_TILE);   // 40960
    const int HG_SMEM_T = 2 * (HG_A_TILE + HG_BT_TILE);  // 37888
    const int EE = E_DIM * E_DIM;

    // ---- fork side streams ----
    cudaEventRecord(evRoot, 0);
    cudaStreamWaitEvent(s1, evRoot, 0);
    cudaStreamWaitEvent(s2, evRoot, 0);

    // s1: value -> fp16 (feeds Y GEMM)
    cvt8_kernel<<<(S_DIM * B_DIM * E_DIM) / 2048, 256, 0, s1>>>(value, vh);
    cudaEventRecord(evV, s1);

    // s2 (high prio): weight converts -> bvo -> wvo -> (wait evV) -> Y halves
    cvt8x4_kernel<<<dim3(EE / 2048, 4), 256, 0, s2>>>(Wq, Wk, Wv, Wo,
                                                      Wqkh, Wqkh + EE, Wvh, Woh);
    cudaEventRecord(evW, s2);
    bvo_kernel<<<128, 256, 0, s2>>>(Wo, bv, bvo);
    hgemm_kernel<true, false, true, false><<<dim3(8, 8, 1), 256, HG_SMEM_T, s2>>>(
        wvoh, Woh, Wvh, nullptr, 1024, 1024, 1024, 1024, 1.0f, 0, 0, 0);
    cudaStreamWaitEvent(s2, evV, 0);
    hmma_y_kernel<<<dim3(2, 256, 1), 256, HMMA_SMEM, s2>>>(yh, vh, wvoh, 0);  // cols 0..511
    cudaEventRecord(evY0, s2);
    hmma_y_kernel<<<dim3(2, 256, 1), 256, HMMA_SMEM, s2>>>(yh, vh, wvoh, 2);  // cols 512..1023
    cudaEventRecord(evY1, s2);

    // main: bias pack, zero la + barriers, mask flags, bucket means
    cudaMemcpyAsync(bqk, bq, E_DIM * sizeof(float), cudaMemcpyDeviceToDevice, 0);
    cudaMemcpyAsync(bqk + E_DIM, bk, E_DIM * sizeof(float), cudaMemcpyDeviceToDevice, 0);
    cudaMemsetAsync(la, 0, (size_t)B_DIM * NB * NB * sizeof(float), 0);
    cudaMemsetAsync(bar, 0, 8 * B_DIM * sizeof(int), 0);
    kpmb_kernel<<<8, 256>>>(kpm, kpmb);
    bucket_mean_h_kernel<<<(B_DIM * NB * E_DIM) / 256, 256>>>(query, qkmh);
    bucket_mean_h_kernel<<<(B_DIM * NB * E_DIM) / 256, 256>>>(key_t, qkmh + QK_STRIDE);

    // main: batched Q+K projection (needs weight cvt)
    cudaStreamWaitEvent(0, evW, 0);
    hgemm_kernel<false, true, true, false><<<dim3(8, 16, 2), 256, HG_SMEM_N>>>(
        qkbh, qkmh, Wqkh, bqk, 2048, 1024, 1024, 1024, 1.0f,
        (long)QK_STRIDE, (long)EE, (long)QK_STRIDE);

    // main: attn logits split-K x2
    hgemm_kernel<false, false, false, true><<<dim3(2, 2, 2 * B_DIM), 256, HG_SMEM_N>>>(
        la, qkbh, qkbh + QK_STRIDE, nullptr, 256, 256, 512, 1024, ATTN_ALPHA,
        (long)NB * E_DIM, (long)NB * E_DIM, (long)NB * NB);

    // main: sinkhorn (32 CTAs, 4 per batch)
    sinkhorn_kernel<<<32, 1024>>>(la, kpmb, ph, rowsum, colpart, bar);

    // main: mix e-half 0 (cols 0..511) overlaps Y half 1
    cudaStreamWaitEvent(0, evY0, 0);
    out_mix_kernel<<<dim3(4, 32, 8), 256, ZSMEM>>>(ph, yh, out, bo, bvo, rowsum, 0);

    // main: mix e-half 1 (cols 512..1023)
    cudaStreamWaitEvent(0, evY1, 0);
    out_mix_kernel<<<dim3(4, 32, 8), 256, ZSMEM>>>(ph, yh, out, bo, bvo, rowsum, 4);
}